// round 14
// baseline (speedup 1.0000x reference)
#include <cuda_runtime.h>
#include <cuda_bf16.h>
#include <cstdint>

// tcgen05 is an arch-specific ('a') feature: only emit in compute_103a/100a.
#if defined(__CUDA_ARCH_FEAT_SM103_ALL) || defined(__CUDA_ARCH_FEAT_SM100_ALL)
#define TC_OK 1
#else
#define TC_OK 0
#endif

#define BATCH 4
#define NTOK 1370
#define CDIM 1024
#define NHEAD 16
#define DHEAD 64
#define MROWS (BATCH*NTOK)   // 5480
#define NPAD 1408            // keys padded (22*64)

// ---------------- scratch ----------------
__device__ float g_q [(size_t)BATCH*NHEAD*NTOK*DHEAD];
__device__ float g_k [(size_t)BATCH*NHEAD*NTOK*DHEAD];
__device__ float g_v [(size_t)BATCH*NHEAD*NTOK*DHEAD];
__device__ float g_ao[(size_t)MROWS*CDIM];
__device__ float g_wqkvT[(size_t)3*CDIM*CDIM];
__device__ float g_wprojT[(size_t)CDIM*CDIM];
__device__ __nv_bfloat16 g_vthb[(size_t)BATCH*NHEAD*DHEAD*NPAD];  // V^T hi (bf16)
__device__ __nv_bfloat16 g_vtlb[(size_t)BATCH*NHEAD*DHEAD*NPAD];  // V^T lo residual (bf16)

// ---------------- helpers ----------------
__device__ __forceinline__ uint32_t smem_u32(const void* p) {
    uint32_t a;
    asm("{ .reg .u64 t; cvta.to.shared.u64 t, %1; cvt.u32.u64 %0, t; }" : "=r"(a) : "l"(p));
    return a;
}
__device__ __forceinline__ uint32_t elect_one() {
    uint32_t pred;
    asm volatile("{\n\t.reg .pred p;\n\telect.sync _|p, 0xFFFFFFFF;\n\tselp.b32 %0, 1, 0, p;\n\t}" : "=r"(pred));
    return pred;
}
__device__ __forceinline__ float tf32r(float x) {
    float y; asm("cvt.rn.tf32.f32 %0, %1;" : "=f"(y) : "f"(x)); return y;
}
__device__ __forceinline__ float ex2f(float x) {
    float y; asm("ex2.approx.ftz.f32 %0, %1;" : "=f"(y) : "f"(x)); return y;
}
__device__ __forceinline__ uint32_t bfpack(float a, float b) {
    __nv_bfloat16 ha = __float2bfloat16(a), hb = __float2bfloat16(b);
    return (uint32_t)*(uint16_t*)&ha | ((uint32_t)*(uint16_t*)&hb << 16);
}
__device__ __forceinline__ void mbar_init(uint32_t mbar, uint32_t cnt) {
    asm volatile("mbarrier.init.shared.b64 [%0], %1;" :: "r"(mbar), "r"(cnt) : "memory");
}
__device__ __forceinline__ void mbar_wait(uint32_t mbar, uint32_t parity) {
    asm volatile(
        "{\n\t.reg .pred P;\n\t"
        "WL_%=:\n\t"
        "mbarrier.try_wait.parity.acquire.cta.shared::cta.b64 P, [%0], %1, 0x989680;\n\t"
        "@P bra.uni WD_%=;\n\t"
        "bra.uni WL_%=;\n\t"
        "WD_%=:\n\t}"
        :: "r"(mbar), "r"(parity) : "memory");
}
__device__ __forceinline__ void fence_async_smem() {
    asm volatile("fence.proxy.async.shared::cta;" ::: "memory");
}

#if TC_OK
#define TCGEN05_ALLOC(sm, n)  asm volatile("tcgen05.alloc.cta_group::1.sync.aligned.shared::cta.b32 [%0], %1;" :: "r"(sm), "r"(n) : "memory")
#define TCGEN05_DEALLOC(t, n) asm volatile("tcgen05.dealloc.cta_group::1.sync.aligned.b32 %0, %1;" :: "r"(t), "r"(n))
#define TCGEN05_RELINQ()      asm volatile("tcgen05.relinquish_alloc_permit.cta_group::1.sync.aligned;")
#define TCGEN05_COMMIT(mb)    asm volatile("tcgen05.commit.cta_group::1.mbarrier::arrive::one.shared::cluster.b64 [%0];" :: "r"(mb) : "memory")
#define TCGEN05_WAIT_LD()     asm volatile("tcgen05.wait::ld.sync.aligned;" ::: "memory")
#define TCGEN05_WAIT_ST()     asm volatile("tcgen05.wait::st.sync.aligned;" ::: "memory")
#define TCGEN05_FENCE_BEFORE() asm volatile("tcgen05.fence::before_thread_sync;" ::: "memory")
#define TCGEN05_FENCE_AFTER()  asm volatile("tcgen05.fence::after_thread_sync;" ::: "memory")

#define TC_LD_X32(r, addr) \
    asm volatile( \
        "tcgen05.ld.sync.aligned.32x32b.x32.b32 " \
        "{%0, %1, %2, %3, %4, %5, %6, %7, " \
        " %8, %9, %10, %11, %12, %13, %14, %15, " \
        " %16, %17, %18, %19, %20, %21, %22, %23, " \
        " %24, %25, %26, %27, %28, %29, %30, %31}, [%32];" \
        : "=r"((r)[0]),  "=r"((r)[1]),  "=r"((r)[2]),  "=r"((r)[3]), \
          "=r"((r)[4]),  "=r"((r)[5]),  "=r"((r)[6]),  "=r"((r)[7]), \
          "=r"((r)[8]),  "=r"((r)[9]),  "=r"((r)[10]), "=r"((r)[11]), \
          "=r"((r)[12]), "=r"((r)[13]), "=r"((r)[14]), "=r"((r)[15]), \
          "=r"((r)[16]), "=r"((r)[17]), "=r"((r)[18]), "=r"((r)[19]), \
          "=r"((r)[20]), "=r"((r)[21]), "=r"((r)[22]), "=r"((r)[23]), \
          "=r"((r)[24]), "=r"((r)[25]), "=r"((r)[26]), "=r"((r)[27]), \
          "=r"((r)[28]), "=r"((r)[29]), "=r"((r)[30]), "=r"((r)[31]) \
        : "r"(addr))

#define TC_ST_X32(addr, r) \
    asm volatile( \
        "tcgen05.st.sync.aligned.32x32b.x32.b32 [%0], " \
        "{%1, %2, %3, %4, %5, %6, %7, %8, " \
        " %9, %10, %11, %12, %13, %14, %15, %16, " \
        " %17, %18, %19, %20, %21, %22, %23, %24, " \
        " %25, %26, %27, %28, %29, %30, %31, %32};" \
        :: "r"(addr), \
           "r"((r)[0]),  "r"((r)[1]),  "r"((r)[2]),  "r"((r)[3]), \
           "r"((r)[4]),  "r"((r)[5]),  "r"((r)[6]),  "r"((r)[7]), \
           "r"((r)[8]),  "r"((r)[9]),  "r"((r)[10]), "r"((r)[11]), \
           "r"((r)[12]), "r"((r)[13]), "r"((r)[14]), "r"((r)[15]), \
           "r"((r)[16]), "r"((r)[17]), "r"((r)[18]), "r"((r)[19]), \
           "r"((r)[20]), "r"((r)[21]), "r"((r)[22]), "r"((r)[23]), \
           "r"((r)[24]), "r"((r)[25]), "r"((r)[26]), "r"((r)[27]), \
           "r"((r)[28]), "r"((r)[29]), "r"((r)[30]), "r"((r)[31]) \
        : "memory")

#define TC_ST_X16(addr, r) \
    asm volatile( \
        "tcgen05.st.sync.aligned.32x32b.x16.b32 [%0], " \
        "{%1, %2, %3, %4, %5, %6, %7, %8, " \
        " %9, %10, %11, %12, %13, %14, %15, %16};" \
        :: "r"(addr), \
           "r"((r)[0]),  "r"((r)[1]),  "r"((r)[2]),  "r"((r)[3]), \
           "r"((r)[4]),  "r"((r)[5]),  "r"((r)[6]),  "r"((r)[7]), \
           "r"((r)[8]),  "r"((r)[9]),  "r"((r)[10]), "r"((r)[11]), \
           "r"((r)[12]), "r"((r)[13]), "r"((r)[14]), "r"((r)[15]) \
        : "memory")

// K-major SW128 descriptor (128B rows)
static __device__ __forceinline__ uint64_t make_desc(uint32_t addr) {
    const uint64_t BASE = (2ull << 61) | (1ull << 46) | (64ull << 32) | (1ull << 16);
    return BASE | ((uint64_t)(addr >> 4) & 0x3FFF);
}
// K-major SW64 descriptor (64B rows; atom 8 rows x 64B; SBO=32, LBO=1)
static __device__ __forceinline__ uint64_t make_desc64(uint32_t addr) {
    const uint64_t BASE = (4ull << 61) | (1ull << 46) | (32ull << 32) | (1ull << 16);
    return BASE | ((uint64_t)(addr >> 4) & 0x3FFF);
}
__device__ __forceinline__ void mma_bf16_ss(uint32_t d, uint64_t ad, uint64_t bd,
                                            uint32_t idesc, bool en) {
    uint32_t e = en ? 1u : 0u;
    asm volatile(
        "{\n\t.reg .pred p;\n\tsetp.ne.u32 p, %4, 0;\n\t"
        "tcgen05.mma.cta_group::1.kind::f16 [%0], %1, %2, %3, {%5, %5, %5, %5}, p;\n\t}"
        :: "r"(d), "l"(ad), "l"(bd), "r"(idesc), "r"(e), "r"(0u) : "memory");
}
__device__ __forceinline__ void mma_bf16_ts(uint32_t d, uint32_t a, uint64_t bd,
                                            uint32_t idesc, bool en) {
    uint32_t e = en ? 1u : 0u;
    asm volatile(
        "{\n\t.reg .pred p;\n\tsetp.ne.u32 p, %4, 0;\n\t"
        "tcgen05.mma.cta_group::1.kind::f16 [%0], [%1], %2, %3, {%5, %5, %5, %5}, p;\n\t}"
        :: "r"(d), "r"(a), "l"(bd), "r"(idesc), "r"(e), "r"(0u) : "memory");
}
#endif // TC_OK

// bf16 idesc: cfmt=F32@[4:5], a/b=BF16(1)@[7:9]/[10:12], N>>3@[17:22], M>>4@[24:28]
static constexpr uint32_t IDESC_BF_128x128 =
    (1u << 4) | (1u << 7) | (1u << 10) | (16u << 17) | (8u << 24);
static constexpr uint32_t IDESC_BF_128x64 =
    (1u << 4) | (1u << 7) | (1u << 10) | (8u << 17) | (8u << 24);

// ---------------------------------------------------------------------------
// prep: transpose both weight matrices in one launch (z selects which).
// ---------------------------------------------------------------------------
__global__ void transpose_w2(const float* __restrict__ wqkv, const float* __restrict__ wproj) {
    const int z = blockIdx.z;
    const int C = z ? CDIM : 3 * CDIM;
    if (blockIdx.x * 32 >= (unsigned)C) return;
    const float* src = z ? wproj : wqkv;
    float* dst = z ? g_wprojT : g_wqkvT;
    __shared__ float t[32][33];
    int bx = blockIdx.x * 32, by = blockIdx.y * 32;
    int txx = threadIdx.x, tyy = threadIdx.y;
    #pragma unroll
    for (int i = 0; i < 4; i++)
        t[tyy + i * 8][txx] = src[(size_t)(by + tyy + i * 8) * C + bx + txx];
    __syncthreads();
    #pragma unroll
    for (int i = 0; i < 4; i++)
        dst[(size_t)(bx + tyy + i * 8) * CDIM + by + txx] = t[txx][tyy + i * 8];
}

// ---------------------------------------------------------------------------
// prep: per-head V transpose + bf16 hi/lo split
// ---------------------------------------------------------------------------
__global__ void transpose_v() {
    __shared__ float t[32][33];
    int bh = blockIdx.z;
    int dt = blockIdx.x * 32, nt = blockIdx.y * 32;
    int txx = threadIdx.x, tyy = threadIdx.y;
    #pragma unroll
    for (int i = 0; i < 4; i++) {
        int n = nt + tyy + i * 8; if (n > NTOK - 1) n = NTOK - 1;
        t[tyy + i * 8][txx] = g_v[((size_t)bh * NTOK + n) * DHEAD + dt + txx];
    }
    __syncthreads();
    #pragma unroll
    for (int i = 0; i < 4; i++) {
        int d = dt + tyy + i * 8;
        float v = t[txx][tyy + i * 8];
        __nv_bfloat16 h = __float2bfloat16(v);
        float r = v - __bfloat162float(h);
        size_t o = ((size_t)bh * DHEAD + d) * NPAD + nt + txx;
        g_vthb[o] = h;
        g_vtlb[o] = __float2bfloat16(r);
    }
}

// ---------------------------------------------------------------------------
// bf16x3 tcgen05 GEMM — unchanged from R13 (passed @617us).
// ---------------------------------------------------------------------------
#define GSMEM_BYTES (1024 + 2 * 32768)

template<int EPI>
__global__ __launch_bounds__(256, 2) void gemm_tc(const float* __restrict__ Aglob,
                                                  const float* __restrict__ Wt,
                                                  const float* __restrict__ bias,
                                                  const float* __restrict__ sinp,
                                                  const float* __restrict__ cosp,
                                                  float* __restrict__ Out, int M) {
#if TC_OK
    extern __shared__ char smem[];
    const uint32_t sb = smem_u32(smem);
    const int K = 1024;
    const int tid = threadIdx.x;
    const int wid = tid >> 5;

    const uint32_t OFF_TM = 0;
    const uint32_t OFF_MB = 16;
    if (wid == 0) { TCGEN05_ALLOC(sb + OFF_TM, 128); TCGEN05_RELINQ(); }
    if (tid == 0) { mbar_init(sb + OFF_MB, 1); mbar_init(sb + OFF_MB + 8, 1); }
    __syncthreads();
    uint32_t tmem;
    asm volatile("ld.shared.b32 %0, [%1];" : "=r"(tmem) : "r"(sb + OFF_TM));

    const int bm = blockIdx.y * 128;
    const int bn = blockIdx.x * 128;

    const int rowA = tid >> 3, c4A = tid & 7;
    float4 ra[4], rb[4];

    auto ldg_tile = [&](int it) {
        const int k0 = it * 32;
        #pragma unroll
        for (int i = 0; i < 4; i++) {
            int row = rowA + i * 32;
            int gr = bm + row;
            ra[i] = (gr < M) ? *(const float4*)&Aglob[(size_t)gr * K + k0 + c4A * 4]
                             : make_float4(0.f, 0.f, 0.f, 0.f);
        }
        #pragma unroll
        for (int i = 0; i < 4; i++) {
            int row = rowA + i * 32;
            rb[i] = *(const float4*)&Wt[(size_t)(bn + row) * K + k0 + c4A * 4];
        }
    };
    auto split_bf = [&](float4 v, uint2& hi, uint2& lo) {
        hi.x = bfpack(v.x, v.y);
        hi.y = bfpack(v.z, v.w);
        float rx = v.x - __bfloat162float(__float2bfloat16(v.x));
        float ry = v.y - __bfloat162float(__float2bfloat16(v.y));
        float rz = v.z - __bfloat162float(__float2bfloat16(v.z));
        float rw = v.w - __bfloat162float(__float2bfloat16(v.w));
        lo.x = bfpack(rx, ry);
        lo.y = bfpack(rz, rw);
    };
    auto sts_tile = [&](int s) {
        const uint32_t stg = 1024u + (uint32_t)s * 32768u;
        #pragma unroll
        for (int i = 0; i < 4; i++) {
            int row = rowA + i * 32;
            uint2 hi, lo;
            split_bf(ra[i], hi, lo);
            uint32_t off = (uint32_t)(row * 64 + c4A * 8);
            off ^= (off >> 3) & 0x30;
            *(uint2*)(smem + stg + off)        = hi;
            *(uint2*)(smem + stg + 8192 + off) = lo;
        }
        #pragma unroll
        for (int i = 0; i < 4; i++) {
            int row = rowA + i * 32;
            uint2 hi, lo;
            split_bf(rb[i], hi, lo);
            uint32_t off = (uint32_t)(row * 64 + c4A * 8);
            off ^= (off >> 3) & 0x30;
            *(uint2*)(smem + stg + 16384 + off) = hi;
            *(uint2*)(smem + stg + 24576 + off) = lo;
        }
        fence_async_smem();
    };

    int ph[2] = {0, 0};
    ldg_tile(0);
    sts_tile(0);
    __syncthreads();

    const int NIT = K / 32;
    for (int it = 0; it < NIT; it++) {
        const int s = it & 1;
        if (it + 1 < NIT) ldg_tile(it + 1);
        if (wid == 0) {
            if (elect_one()) {
                const uint32_t stg = 1024u + (uint32_t)s * 32768u;
                uint64_t dAh = make_desc64(sb + stg);
                uint64_t dAl = make_desc64(sb + stg + 8192);
                uint64_t dBh = make_desc64(sb + stg + 16384);
                uint64_t dBl = make_desc64(sb + stg + 24576);
                #pragma unroll
                for (int ks = 0; ks < 2; ks++)
                    mma_bf16_ss(tmem, dAh + ks * 2, dBh + ks * 2, IDESC_BF_128x128, (it > 0) || (ks > 0));
                #pragma unroll
                for (int ks = 0; ks < 2; ks++)
                    mma_bf16_ss(tmem, dAl + ks * 2, dBh + ks * 2, IDESC_BF_128x128, true);
                #pragma unroll
                for (int ks = 0; ks < 2; ks++)
                    mma_bf16_ss(tmem, dAh + ks * 2, dBl + ks * 2, IDESC_BF_128x128, true);
                TCGEN05_COMMIT(sb + OFF_MB + s * 8);
            }
        }
        if (it + 1 < NIT) {
            const int so = s ^ 1;
            if (it >= 1) { mbar_wait(sb + OFF_MB + so * 8, ph[so]); ph[so] ^= 1; }
            sts_tile(so);
        }
        __syncthreads();
    }
    mbar_wait(sb + OFF_MB + ((NIT - 1) & 1) * 8, ph[(NIT - 1) & 1]);
    TCGEN05_FENCE_AFTER();

    if (tid < 128) {
        const int r = bm + tid;
        if (EPI == 0) {
            #pragma unroll
            for (int hb = 0; hb < 128; hb += 64) {
                uint32_t dr[64];
                TC_LD_X32(dr, tmem + hb);
                TC_LD_X32(dr + 32, tmem + hb + 32);
                TCGEN05_WAIT_LD();
                if (r < M) {
                    const int c0 = bn + hb;
                    const int which = c0 >> 10;
                    const int h = (c0 & 1023) >> 6;
                    float vbuf[64];
                    #pragma unroll
                    for (int j = 0; j < 64; j++)
                        vbuf[j] = __uint_as_float(dr[j]) + bias[c0 + j];
                    const int b = r / NTOK, n = r % NTOK;
                    if (which < 2 && n >= 1) {
                        const float* sr = &sinp[(size_t)(n - 1) * DHEAD];
                        const float* cr = &cosp[(size_t)(n - 1) * DHEAD];
                        #pragma unroll
                        for (int d = 0; d < 32; d++) {
                            float x1 = vbuf[d], x2 = vbuf[d + 32];
                            vbuf[d]      = x1 * cr[d]      - x2 * sr[d];
                            vbuf[d + 32] = x2 * cr[d + 32] + x1 * sr[d + 32];
                        }
                    }
                    float* dst = (which == 0) ? g_q : (which == 1) ? g_k : g_v;
                    size_t base = (((size_t)b * NHEAD + h) * NTOK + n) * DHEAD;
                    #pragma unroll
                    for (int d = 0; d < 64; d += 4)
                        *(float4*)&dst[base + d] = make_float4(vbuf[d], vbuf[d+1], vbuf[d+2], vbuf[d+3]);
                }
            }
        } else {
            #pragma unroll
            for (int cb = 0; cb < 128; cb += 32) {
                uint32_t dr[32];
                TC_LD_X32(dr, tmem + cb);
                TCGEN05_WAIT_LD();
                if (r < M) {
                    const int c0 = bn + cb;
                    #pragma unroll
                    for (int j = 0; j < 32; j += 4) {
                        float4 v = make_float4(__uint_as_float(dr[j])     + bias[c0 + j],
                                               __uint_as_float(dr[j + 1]) + bias[c0 + j + 1],
                                               __uint_as_float(dr[j + 2]) + bias[c0 + j + 2],
                                               __uint_as_float(dr[j + 3]) + bias[c0 + j + 3]);
                        *(float4*)&Out[(size_t)r * CDIM + c0 + j] = v;
                    }
                }
            }
        }
    }
    __syncthreads();
    if (wid == 0) TCGEN05_DEALLOC(tmem, 128);
#endif
}

// ---------------------------------------------------------------------------
// Tensor-core flash attention, bf16x3, 64-key chunks (R6 ordering skeleton).
// TMEM (256): O@0(64 fp32), S@64(64 fp32), Ph@128(32 bf16x2), Pl@160(32),
//             Qh@192(32 bf16x2), Ql@224(32)
// SMEM: hdr 1KB; stage b: K hi@1024+b*16384 (8KB), K lo +8192;
//       V hi@33792+b*16384 (8KB), V lo +8192.  Total 66.5KB -> 2 CTAs/SM.
// S: 12 bf16 MMAs (Qh*Kh + Ql*Kh + Qh*Kl);  PV: 12 bf16 MMAs (Ph*Vh+Pl*Vh+Ph*Vl)
// ---------------------------------------------------------------------------
#define ATT_SMEM 66560
#define NCHUNK 22

__global__ __launch_bounds__(256, 2) void attn_tc() {
#if TC_OK
    extern __shared__ char smem[];
    const uint32_t sb = smem_u32(smem);
    const int tid = threadIdx.x;
    const int wid = tid >> 5;
    const int bh = blockIdx.y;
    const int qt = blockIdx.x;
    const uint32_t MB_S = sb + 8, MB_O = sb + 16;

    if (wid == 0) { TCGEN05_ALLOC(sb, 256); TCGEN05_RELINQ(); }
    if (tid == 0) { mbar_init(MB_S, 1); mbar_init(MB_O, 1); }
    __syncthreads();
    uint32_t tmem;
    asm volatile("ld.shared.b32 %0, [%1];" : "=r"(tmem) : "r"(sb));

    // ---- Q bf16 hi/lo -> TMEM (Qh@192, Ql@224) ----
    if (tid < 128) {
        int qrow = qt * 128 + tid; if (qrow > NTOK - 1) qrow = NTOK - 1;
        const float* Qp = g_q + ((size_t)bh * NTOK + qrow) * DHEAD;
        uint32_t qh[32], ql[32];
        #pragma unroll
        for (int i = 0; i < 32; i++) {
            float a = Qp[2 * i], b = Qp[2 * i + 1];
            qh[i] = bfpack(a, b);
            float ra = a - __bfloat162float(__float2bfloat16(a));
            float rb = b - __bfloat162float(__float2bfloat16(b));
            ql[i] = bfpack(ra, rb);
        }
        uint32_t woff = (uint32_t)(tid >> 5) << 21;
        TC_ST_X32(tmem + 192 + woff, qh);
        TC_ST_X32(tmem + 224 + woff, ql);
        TCGEN05_WAIT_ST();
        TCGEN05_FENCE_BEFORE();
    }

    auto load_chunk = [&](int c, int b) {
        const int k0 = c * 64;
        const uint32_t kb = 1024u  + (uint32_t)b * 16384u;
        const uint32_t vb = 33792u + (uint32_t)b * 16384u;
        // K tile [64 key-rows][64 d bf16] = 128B/row SW128; per thread 16 floats
        {
            int row = tid >> 2, seg = tid & 3;
            int gk = k0 + row; if (gk > NTOK - 1) gk = NTOK - 1;
            const float* src = &g_k[((size_t)bh * NTOK + gk) * DHEAD + seg * 16];
            uint32_t hiw[8], low[8];
            #pragma unroll
            for (int j = 0; j < 8; j++) {
                float a = src[2 * j], b2 = src[2 * j + 1];
                hiw[j] = bfpack(a, b2);
                float ra = a - __bfloat162float(__float2bfloat16(a));
                float rb = b2 - __bfloat162float(__float2bfloat16(b2));
                low[j] = bfpack(ra, rb);
            }
            #pragma unroll
            for (int h = 0; h < 2; h++) {
                uint32_t off = (uint32_t)(row * 128) +
                               (((uint32_t)(seg * 32 + h * 16)) ^ (uint32_t)((row & 7) << 4));
                *(uint4*)(smem + kb + off)        = make_uint4(hiw[h*4], hiw[h*4+1], hiw[h*4+2], hiw[h*4+3]);
                *(uint4*)(smem + kb + 8192 + off) = make_uint4(low[h*4], low[h*4+1], low[h*4+2], low[h*4+3]);
            }
        }
        // V tile [64 d-rows][64 keys bf16] = 128B/row SW128; per thread 16 bf16 each
        {
            int row = tid >> 2, seg = tid & 3;
            const __nv_bfloat16* sh = &g_vthb[((size_t)bh * DHEAD + row) * NPAD + k0 + seg * 16];
            const __nv_bfloat16* sl = &g_vtlb[((size_t)bh * DHEAD + row) * NPAD + k0 + seg * 16];
            uint4 h0 = *(const uint4*)sh;
            uint4 l0 = *(const uint4*)sl;
            uint32_t off = (uint32_t)(row * 128) +
                           (((uint32_t)(seg * 32)) ^ (uint32_t)((row & 7) << 4));
            *(uint4*)(smem + vb + off)        = h0;
            *(uint4*)(smem + vb + 8192 + off) = l0;
            uint4 h1 = *(const uint4*)(sh + 8);
            uint4 l1 = *(const uint4*)(sl + 8);
            uint32_t off1 = (uint32_t)(row * 128) +
                            (((uint32_t)(seg * 32 + 16)) ^ (uint32_t)((row & 7) << 4));
            *(uint4*)(smem + vb + off1)        = h1;
            *(uint4*)(smem + vb + 8192 + off1) = l1;
        }
        fence_async_smem();
    };

    load_chunk(0, 0);
    __syncthreads();

    float l = 0.f;
    const float C1 = 0.18033688011112042f;     // 0.125 * log2(e)
    const uint32_t subp = (uint32_t)(wid & 3) << 21;
    const uint32_t colh = (uint32_t)(wid >> 2) << 5;   // 0 or 32 (fp32 S cols)
    const int jbase = (wid >> 2) * 32;

    for (int c = 0; c < NCHUNK; c++) {
        const int b = c & 1;
        // S-MMA(c): S[128,64] = bf16x3( Q * K(b)^T ), K dim = 64 d, 4 steps
        if (wid == 0) {
            TCGEN05_FENCE_AFTER();
            if (elect_one()) {
                uint64_t dKh = make_desc(sb + 1024u + (uint32_t)b * 16384u);
                uint64_t dKl = make_desc(sb + 1024u + (uint32_t)b * 16384u + 8192u);
                #pragma unroll
                for (int ks = 0; ks < 4; ks++)
                    mma_bf16_ts(tmem + 64, tmem + 192 + ks * 8, dKh + ks * 2, IDESC_BF_128x64, ks > 0);
                #pragma unroll
                for (int ks = 0; ks < 4; ks++)
                    mma_bf16_ts(tmem + 64, tmem + 224 + ks * 8, dKh + ks * 2, IDESC_BF_128x64, true);
                #pragma unroll
                for (int ks = 0; ks < 4; ks++)
                    mma_bf16_ts(tmem + 64, tmem + 192 + ks * 8, dKl + ks * 2, IDESC_BF_128x64, true);
                TCGEN05_COMMIT(MB_S);
            }
        }
        if (c >= 1) mbar_wait(MB_O, (c - 1) & 1);     // PV(c-1) done
        if (c + 1 < NCHUNK) load_chunk(c + 1, b ^ 1);

        // ---- softmax: 8 warps, 32 S cols each ----
        mbar_wait(MB_S, c & 1);
        TCGEN05_FENCE_AFTER();
        {
            uint32_t sr[32];
            TC_LD_X32(sr, tmem + 64 + colh + subp);
            TCGEN05_WAIT_LD();
            const int nk = NTOK - c * 64;
            float p[32];
            float lsum = 0.f;
            #pragma unroll
            for (int j = 0; j < 32; j++) {
                float s = __uint_as_float(sr[j]);
                float pp = ex2f(fmaf(s, C1, -40.f));
                if (jbase + j >= nk) pp = 0.f;
                lsum += pp;
                p[j] = pp;
            }
            l += lsum;
            uint32_t phw[16], plw[16];
            #pragma unroll
            for (int j = 0; j < 16; j++) {
                float a = p[2 * j], b2 = p[2 * j + 1];
                phw[j] = bfpack(a, b2);
                float ra = a - __bfloat162float(__float2bfloat16(a));
                float rb = b2 - __bfloat162float(__float2bfloat16(b2));
                plw[j] = bfpack(ra, rb);
            }
            const uint32_t pco = (uint32_t)(wid >> 2) * 16 + subp;
            TC_ST_X16(tmem + 128 + pco, phw);
            TC_ST_X16(tmem + 160 + pco, plw);
            TCGEN05_WAIT_ST();
            TCGEN05_FENCE_BEFORE();
        }
        __syncthreads();
        // PV(c): O[128,64] += Ph*Vh + Pl*Vh + Ph*Vl (K dim = 64 keys, 4 steps)
        if (wid == 0) {
            TCGEN05_FENCE_AFTER();
            if (elect_one()) {
                uint64_t dVh = make_desc(sb + 33792u + (uint32_t)b * 16384u);
                uint64_t dVl = make_desc(sb + 33792u + (uint32_t)b * 16384u + 8192u);
                #pragma unroll
                for (int ks = 0; ks < 4; ks++)
                    mma_bf16_ts(tmem + 0, tmem + 128 + ks * 8, dVh + ks * 2, IDESC_BF_128x64, (c > 0) || (ks > 0));
                #pragma unroll
                for (int ks = 0; ks < 4; ks++)
                    mma_bf16_ts(tmem + 0, tmem + 160 + ks * 8, dVh + ks * 2, IDESC_BF_128x64, true);
                #pragma unroll
                for (int ks = 0; ks < 4; ks++)
                    mma_bf16_ts(tmem + 0, tmem + 128 + ks * 8, dVl + ks * 2, IDESC_BF_128x64, true);
                TCGEN05_COMMIT(MB_O);
            }
        }
    }

    mbar_wait(MB_O, (NCHUNK - 1) & 1);
    TCGEN05_FENCE_AFTER();
    // combine l partials: warps 4-7 publish, warps 0-3 add
    if (wid >= 4) ((float*)(smem + 512))[tid - 128] = l;
    __syncthreads();
    if (tid < 128) {
        float ltot = l + ((float*)(smem + 512))[tid];
        uint32_t o1[32], o2[32];
        TC_LD_X32(o1, tmem + 0);
        TC_LD_X32(o2, tmem + 32);
        TCGEN05_WAIT_LD();
        int qrow = qt * 128 + tid;
        if (qrow < NTOK) {
            float inv = 1.f / ltot;
            int bb = bh >> 4, h = bh & 15;
            size_t base = ((size_t)(bb * NTOK + qrow)) * CDIM + h * DHEAD;
            #pragma unroll
            for (int d = 0; d < 32; d += 4)
                *(float4*)&g_ao[base + d] = make_float4(
                    __uint_as_float(o1[d]) * inv, __uint_as_float(o1[d+1]) * inv,
                    __uint_as_float(o1[d+2]) * inv, __uint_as_float(o1[d+3]) * inv);
            #pragma unroll
            for (int d = 0; d < 32; d += 4)
                *(float4*)&g_ao[base + 32 + d] = make_float4(
                    __uint_as_float(o2[d]) * inv, __uint_as_float(o2[d+1]) * inv,
                    __uint_as_float(o2[d+2]) * inv, __uint_as_float(o2[d+3]) * inv);
        }
    }
    __syncthreads();
    if (wid == 0) TCGEN05_DEALLOC(tmem, 256);
#endif
}

// ---------------------------------------------------------------------------
extern "C" void kernel_launch(void* const* d_in, const int* in_sizes, int n_in,
                              void* d_out, int out_size) {
    const float* x      = (const float*)d_in[0];
    const float* sinp   = (const float*)d_in[1];
    const float* cosp   = (const float*)d_in[2];
    const float* w_qkv  = (const float*)d_in[3];
    const float* b_qkv  = (const float*)d_in[4];
    const float* w_proj = (const float*)d_in[5];
    const float* b_proj = (const float*)d_in[6];
    float* out = (float*)d_out;

    cudaFuncSetAttribute(gemm_tc<0>, cudaFuncAttributeMaxDynamicSharedMemorySize, GSMEM_BYTES);
    cudaFuncSetAttribute(gemm_tc<1>, cudaFuncAttributeMaxDynamicSharedMemorySize, GSMEM_BYTES);
    cudaFuncSetAttribute(attn_tc,    cudaFuncAttributeMaxDynamicSharedMemorySize, ATT_SMEM);

    float* wqt; cudaGetSymbolAddress((void**)&wqt, g_wqkvT);
    float* wpt; cudaGetSymbolAddress((void**)&wpt, g_wprojT);
    float* ao;  cudaGetSymbolAddress((void**)&ao,  g_ao);

    transpose_w2<<<dim3(3 * CDIM / 32, CDIM / 32, 2), dim3(32, 8)>>>(w_qkv, w_proj);

    dim3 gq(3 * CDIM / 128, (MROWS + 127) / 128);   // 24 x 43
    gemm_tc<0><<<gq, 256, GSMEM_BYTES>>>(x, wqt, b_qkv, sinp, cosp, nullptr, MROWS);

    transpose_v<<<dim3(2, NPAD / 32, BATCH * NHEAD), dim3(32, 8)>>>();

    dim3 ga((NTOK + 127) / 128, BATCH * NHEAD);     // 11 x 64
    attn_tc<<<ga, 256, ATT_SMEM>>>();

    dim3 gp(CDIM / 128, (MROWS + 127) / 128);       // 8 x 43
    gemm_tc<1><<<gp, 256, GSMEM_BYTES>>>(ao, wpt, b_proj, nullptr, nullptr, out, MROWS);
}

// round 15
// speedup vs baseline: 1.1490x; 1.1490x over previous
#include <cuda_runtime.h>
#include <cuda_bf16.h>
#include <cstdint>

// tcgen05 is an arch-specific ('a') feature: only emit in compute_103a/100a.
#if defined(__CUDA_ARCH_FEAT_SM103_ALL) || defined(__CUDA_ARCH_FEAT_SM100_ALL)
#define TC_OK 1
#else
#define TC_OK 0
#endif

#define BATCH 4
#define NTOK 1370
#define CDIM 1024
#define NHEAD 16
#define DHEAD 64
#define MROWS (BATCH*NTOK)   // 5480
#define NPAD 1408

// ---------------- scratch ----------------
__device__ float g_q [(size_t)BATCH*NHEAD*NTOK*DHEAD];
__device__ float g_k [(size_t)BATCH*NHEAD*NTOK*DHEAD];
__device__ float g_v [(size_t)BATCH*NHEAD*NTOK*DHEAD];
__device__ float g_vth[(size_t)BATCH*NHEAD*DHEAD*NPAD];  // V^T hi (tf32)
__device__ float g_vtl[(size_t)BATCH*NHEAD*DHEAD*NPAD];  // V^T lo residual
// pre-split bf16 operand planes for the GEMMs
__device__ __nv_bfloat16 g_xh[(size_t)MROWS*CDIM];
__device__ __nv_bfloat16 g_xl[(size_t)MROWS*CDIM];
__device__ __nv_bfloat16 g_wqh[(size_t)3*CDIM*CDIM];   // w_qkv^T hi
__device__ __nv_bfloat16 g_wql[(size_t)3*CDIM*CDIM];   // w_qkv^T lo
__device__ __nv_bfloat16 g_wph[(size_t)CDIM*CDIM];     // w_proj^T hi
__device__ __nv_bfloat16 g_wpl[(size_t)CDIM*CDIM];     // w_proj^T lo
__device__ __nv_bfloat16 g_aoh[(size_t)MROWS*CDIM];    // attention out hi
__device__ __nv_bfloat16 g_aol[(size_t)MROWS*CDIM];    // attention out lo

// ---------------- helpers ----------------
__device__ __forceinline__ uint32_t smem_u32(const void* p) {
    uint32_t a;
    asm("{ .reg .u64 t; cvta.to.shared.u64 t, %1; cvt.u32.u64 %0, t; }" : "=r"(a) : "l"(p));
    return a;
}
__device__ __forceinline__ uint32_t elect_one() {
    uint32_t pred;
    asm volatile("{\n\t.reg .pred p;\n\telect.sync _|p, 0xFFFFFFFF;\n\tselp.b32 %0, 1, 0, p;\n\t}" : "=r"(pred));
    return pred;
}
__device__ __forceinline__ float tf32r(float x) {
    float y; asm("cvt.rn.tf32.f32 %0, %1;" : "=f"(y) : "f"(x)); return y;
}
__device__ __forceinline__ float ex2f(float x) {
    float y; asm("ex2.approx.ftz.f32 %0, %1;" : "=f"(y) : "f"(x)); return y;
}
__device__ __forceinline__ uint32_t bfpack(float a, float b) {
    __nv_bfloat16 ha = __float2bfloat16(a), hb = __float2bfloat16(b);
    return (uint32_t)*(uint16_t*)&ha | ((uint32_t)*(uint16_t*)&hb << 16);
}
__device__ __forceinline__ void mbar_init(uint32_t mbar, uint32_t cnt) {
    asm volatile("mbarrier.init.shared.b64 [%0], %1;" :: "r"(mbar), "r"(cnt) : "memory");
}
__device__ __forceinline__ void mbar_wait(uint32_t mbar, uint32_t parity) {
    asm volatile(
        "{\n\t.reg .pred P;\n\t"
        "WL_%=:\n\t"
        "mbarrier.try_wait.parity.acquire.cta.shared::cta.b64 P, [%0], %1, 0x989680;\n\t"
        "@P bra.uni WD_%=;\n\t"
        "bra.uni WL_%=;\n\t"
        "WD_%=:\n\t}"
        :: "r"(mbar), "r"(parity) : "memory");
}
__device__ __forceinline__ void fence_async_smem() {
    asm volatile("fence.proxy.async.shared::cta;" ::: "memory");
}

#if TC_OK
#define TCGEN05_ALLOC(sm, n)  asm volatile("tcgen05.alloc.cta_group::1.sync.aligned.shared::cta.b32 [%0], %1;" :: "r"(sm), "r"(n) : "memory")
#define TCGEN05_DEALLOC(t, n) asm volatile("tcgen05.dealloc.cta_group::1.sync.aligned.b32 %0, %1;" :: "r"(t), "r"(n))
#define TCGEN05_RELINQ()      asm volatile("tcgen05.relinquish_alloc_permit.cta_group::1.sync.aligned;")
#define TCGEN05_COMMIT(mb)    asm volatile("tcgen05.commit.cta_group::1.mbarrier::arrive::one.shared::cluster.b64 [%0];" :: "r"(mb) : "memory")
#define TCGEN05_WAIT_LD()     asm volatile("tcgen05.wait::ld.sync.aligned;" ::: "memory")
#define TCGEN05_WAIT_ST()     asm volatile("tcgen05.wait::st.sync.aligned;" ::: "memory")
#define TCGEN05_FENCE_BEFORE() asm volatile("tcgen05.fence::before_thread_sync;" ::: "memory")
#define TCGEN05_FENCE_AFTER()  asm volatile("tcgen05.fence::after_thread_sync;" ::: "memory")

#define TC_LD_X32(r, addr) \
    asm volatile( \
        "tcgen05.ld.sync.aligned.32x32b.x32.b32 " \
        "{%0, %1, %2, %3, %4, %5, %6, %7, " \
        " %8, %9, %10, %11, %12, %13, %14, %15, " \
        " %16, %17, %18, %19, %20, %21, %22, %23, " \
        " %24, %25, %26, %27, %28, %29, %30, %31}, [%32];" \
        : "=r"((r)[0]),  "=r"((r)[1]),  "=r"((r)[2]),  "=r"((r)[3]), \
          "=r"((r)[4]),  "=r"((r)[5]),  "=r"((r)[6]),  "=r"((r)[7]), \
          "=r"((r)[8]),  "=r"((r)[9]),  "=r"((r)[10]), "=r"((r)[11]), \
          "=r"((r)[12]), "=r"((r)[13]), "=r"((r)[14]), "=r"((r)[15]), \
          "=r"((r)[16]), "=r"((r)[17]), "=r"((r)[18]), "=r"((r)[19]), \
          "=r"((r)[20]), "=r"((r)[21]), "=r"((r)[22]), "=r"((r)[23]), \
          "=r"((r)[24]), "=r"((r)[25]), "=r"((r)[26]), "=r"((r)[27]), \
          "=r"((r)[28]), "=r"((r)[29]), "=r"((r)[30]), "=r"((r)[31]) \
        : "r"(addr))

#define TC_ST_X32(addr, r) \
    asm volatile( \
        "tcgen05.st.sync.aligned.32x32b.x32.b32 [%0], " \
        "{%1, %2, %3, %4, %5, %6, %7, %8, " \
        " %9, %10, %11, %12, %13, %14, %15, %16, " \
        " %17, %18, %19, %20, %21, %22, %23, %24, " \
        " %25, %26, %27, %28, %29, %30, %31, %32};" \
        :: "r"(addr), \
           "r"((r)[0]),  "r"((r)[1]),  "r"((r)[2]),  "r"((r)[3]), \
           "r"((r)[4]),  "r"((r)[5]),  "r"((r)[6]),  "r"((r)[7]), \
           "r"((r)[8]),  "r"((r)[9]),  "r"((r)[10]), "r"((r)[11]), \
           "r"((r)[12]), "r"((r)[13]), "r"((r)[14]), "r"((r)[15]), \
           "r"((r)[16]), "r"((r)[17]), "r"((r)[18]), "r"((r)[19]), \
           "r"((r)[20]), "r"((r)[21]), "r"((r)[22]), "r"((r)[23]), \
           "r"((r)[24]), "r"((r)[25]), "r"((r)[26]), "r"((r)[27]), \
           "r"((r)[28]), "r"((r)[29]), "r"((r)[30]), "r"((r)[31]) \
        : "memory")

#define TC_LD_X16(r, addr) \
    asm volatile( \
        "tcgen05.ld.sync.aligned.32x32b.x16.b32 " \
        "{%0, %1, %2, %3, %4, %5, %6, %7, " \
        " %8, %9, %10, %11, %12, %13, %14, %15}, [%16];" \
        : "=r"((r)[0]),  "=r"((r)[1]),  "=r"((r)[2]),  "=r"((r)[3]), \
          "=r"((r)[4]),  "=r"((r)[5]),  "=r"((r)[6]),  "=r"((r)[7]), \
          "=r"((r)[8]),  "=r"((r)[9]),  "=r"((r)[10]), "=r"((r)[11]), \
          "=r"((r)[12]), "=r"((r)[13]), "=r"((r)[14]), "=r"((r)[15]) \
        : "r"(addr))

#define TC_ST_X16(addr, r) \
    asm volatile( \
        "tcgen05.st.sync.aligned.32x32b.x16.b32 [%0], " \
        "{%1, %2, %3, %4, %5, %6, %7, %8, " \
        " %9, %10, %11, %12, %13, %14, %15, %16};" \
        :: "r"(addr), \
           "r"((r)[0]),  "r"((r)[1]),  "r"((r)[2]),  "r"((r)[3]), \
           "r"((r)[4]),  "r"((r)[5]),  "r"((r)[6]),  "r"((r)[7]), \
           "r"((r)[8]),  "r"((r)[9]),  "r"((r)[10]), "r"((r)[11]), \
           "r"((r)[12]), "r"((r)[13]), "r"((r)[14]), "r"((r)[15]) \
        : "memory")

// K-major SW128 descriptor (128B rows)
static __device__ __forceinline__ uint64_t make_desc(uint32_t addr) {
    const uint64_t BASE = (2ull << 61) | (1ull << 46) | (64ull << 32) | (1ull << 16);
    return BASE | ((uint64_t)(addr >> 4) & 0x3FFF);
}
// K-major SW64 descriptor (64B rows; atom 8 rows x 64B; SBO=32, LBO=1)
static __device__ __forceinline__ uint64_t make_desc64(uint32_t addr) {
    const uint64_t BASE = (4ull << 61) | (1ull << 46) | (32ull << 32) | (1ull << 16);
    return BASE | ((uint64_t)(addr >> 4) & 0x3FFF);
}
__device__ __forceinline__ void mma_tf32_ts(uint32_t d, uint32_t a, uint64_t bd,
                                            uint32_t idesc, bool en) {
    uint32_t e = en ? 1u : 0u;
    asm volatile(
        "{\n\t.reg .pred p;\n\tsetp.ne.u32 p, %4, 0;\n\t"
        "tcgen05.mma.cta_group::1.kind::tf32 [%0], [%1], %2, %3, {%5, %5, %5, %5}, p;\n\t}"
        :: "r"(d), "r"(a), "l"(bd), "r"(idesc), "r"(e), "r"(0u) : "memory");
}
__device__ __forceinline__ void mma_bf16_ss(uint32_t d, uint64_t ad, uint64_t bd,
                                            uint32_t idesc, bool en) {
    uint32_t e = en ? 1u : 0u;
    asm volatile(
        "{\n\t.reg .pred p;\n\tsetp.ne.u32 p, %4, 0;\n\t"
        "tcgen05.mma.cta_group::1.kind::f16 [%0], %1, %2, %3, {%5, %5, %5, %5}, p;\n\t}"
        :: "r"(d), "l"(ad), "l"(bd), "r"(idesc), "r"(e), "r"(0u) : "memory");
}
#endif // TC_OK

static constexpr uint32_t IDESC_BF_128x128 =
    (1u << 4) | (1u << 7) | (1u << 10) | (16u << 17) | (8u << 24);
static constexpr uint32_t IDESC_128x32 =
    (1u << 4) | (2u << 7) | (2u << 10) | (4u << 17) | (8u << 24);
static constexpr uint32_t IDESC_128x64 =
    (1u << 4) | (2u << 7) | (2u << 10) | (8u << 17) | (8u << 24);

// ---------------------------------------------------------------------------
// prep: elementwise bf16 hi/lo split of x
// ---------------------------------------------------------------------------
__global__ void split_x(const float* __restrict__ x) {
    int i = blockIdx.x * blockDim.x + threadIdx.x;
    const int total = MROWS * CDIM / 4;
    if (i >= total) return;
    float4 v = ((const float4*)x)[i];
    uint2 hi, lo;
    hi.x = bfpack(v.x, v.y); hi.y = bfpack(v.z, v.w);
    float rx = v.x - __bfloat162float(__float2bfloat16(v.x));
    float ry = v.y - __bfloat162float(__float2bfloat16(v.y));
    float rz = v.z - __bfloat162float(__float2bfloat16(v.z));
    float rw = v.w - __bfloat162float(__float2bfloat16(v.w));
    lo.x = bfpack(rx, ry); lo.y = bfpack(rz, rw);
    ((uint2*)g_xh)[i] = hi;
    ((uint2*)g_xl)[i] = lo;
}

// ---------------------------------------------------------------------------
// prep: transpose both weight matrices + bf16 hi/lo split, one launch.
// ---------------------------------------------------------------------------
__global__ void transpose_w2(const float* __restrict__ wqkv, const float* __restrict__ wproj) {
    const int z = blockIdx.z;
    const int C = z ? CDIM : 3 * CDIM;
    if (blockIdx.x * 32 >= (unsigned)C) return;
    const float* src = z ? wproj : wqkv;
    __nv_bfloat16* dh = z ? g_wph : g_wqh;
    __nv_bfloat16* dl = z ? g_wpl : g_wql;
    __shared__ float t[32][33];
    int bx = blockIdx.x * 32, by = blockIdx.y * 32;
    int txx = threadIdx.x, tyy = threadIdx.y;
    #pragma unroll
    for (int i = 0; i < 4; i++)
        t[tyy + i * 8][txx] = src[(size_t)(by + tyy + i * 8) * C + bx + txx];
    __syncthreads();
    #pragma unroll
    for (int i = 0; i < 4; i++) {
        float v = t[txx][tyy + i * 8];
        __nv_bfloat16 h = __float2bfloat16(v);
        float r = v - __bfloat162float(h);
        size_t o = (size_t)(bx + tyy + i * 8) * CDIM + by + txx;
        dh[o] = h;
        dl[o] = __float2bfloat16(r);
    }
}

// ---------------------------------------------------------------------------
// prep: per-head V transpose + tf32 hi/lo split (for attention PV, as R13)
// ---------------------------------------------------------------------------
__global__ void transpose_v() {
    __shared__ float t[32][33];
    int bh = blockIdx.z;
    int dt = blockIdx.x * 32, nt = blockIdx.y * 32;
    int txx = threadIdx.x, tyy = threadIdx.y;
    #pragma unroll
    for (int i = 0; i < 4; i++) {
        int n = nt + tyy + i * 8; if (n > NTOK - 1) n = NTOK - 1;
        t[tyy + i * 8][txx] = g_v[((size_t)bh * NTOK + n) * DHEAD + dt + txx];
    }
    __syncthreads();
    #pragma unroll
    for (int i = 0; i < 4; i++) {
        int d = dt + tyy + i * 8;
        float v = t[txx][tyy + i * 8];
        float h = tf32r(v);
        size_t o = ((size_t)bh * DHEAD + d) * NPAD + nt + txx;
        g_vth[o] = h;
        g_vtl[o] = v - h;
    }
}

// ---------------------------------------------------------------------------
// bf16x3 tcgen05 GEMM, operands PRE-SPLIT in gmem -> loader is pure copy.
// Tile 128x128, BK=32, SW64 (64B rows), 2-stage, 2 CTAs/SM. R13 MMA schedule.
// stage layout: Ah@0, Al@8192, Bh@16384, Bl@24576 (8KB each)
// ---------------------------------------------------------------------------
#define GSMEM_BYTES (1024 + 2 * 32768)

template<int EPI>
__global__ __launch_bounds__(256, 2) void gemm_tc(const __nv_bfloat16* __restrict__ Ah,
                                                  const __nv_bfloat16* __restrict__ Al,
                                                  const __nv_bfloat16* __restrict__ Bh,
                                                  const __nv_bfloat16* __restrict__ Bl,
                                                  const float* __restrict__ bias,
                                                  const float* __restrict__ sinp,
                                                  const float* __restrict__ cosp,
                                                  float* __restrict__ Out, int M) {
#if TC_OK
    extern __shared__ char smem[];
    const uint32_t sb = smem_u32(smem);
    const int K = 1024;
    const int tid = threadIdx.x;
    const int wid = tid >> 5;

    const uint32_t OFF_TM = 0;
    const uint32_t OFF_MB = 16;
    if (wid == 0) { TCGEN05_ALLOC(sb + OFF_TM, 128); TCGEN05_RELINQ(); }
    if (tid == 0) { mbar_init(sb + OFF_MB, 1); mbar_init(sb + OFF_MB + 8, 1); }
    __syncthreads();
    uint32_t tmem;
    asm volatile("ld.shared.b32 %0, [%1];" : "=r"(tmem) : "r"(sb + OFF_TM));

    const int bm = blockIdx.y * 128;
    const int bn = blockIdx.x * 128;

    // 128 rows x 64B per region; idx = tid + i*256, row = idx>>2, seg = idx&3
    uint4 rah[2], ral[2], rbh[2], rbl[2];

    auto ldg_tile = [&](int it) {
        const int k0 = it * 32;
        #pragma unroll
        for (int i = 0; i < 2; i++) {
            int idx = tid + i * 256;
            int row = idx >> 2, seg = idx & 3;
            int gr = bm + row;
            int grc = (gr < M) ? gr : (M - 1);
            size_t ao = (size_t)grc * K + k0 + seg * 8;
            rah[i] = *(const uint4*)&Ah[ao];
            ral[i] = *(const uint4*)&Al[ao];
            if (gr >= M) { rah[i] = make_uint4(0,0,0,0); ral[i] = make_uint4(0,0,0,0); }
            size_t bo = (size_t)(bn + row) * K + k0 + seg * 8;
            rbh[i] = *(const uint4*)&Bh[bo];
            rbl[i] = *(const uint4*)&Bl[bo];
        }
    };
    auto sts_tile = [&](int s) {
        const uint32_t stg = 1024u + (uint32_t)s * 32768u;
        #pragma unroll
        for (int i = 0; i < 2; i++) {
            int idx = tid + i * 256;
            int row = idx >> 2, seg = idx & 3;
            uint32_t off = (uint32_t)(row * 64 + seg * 16);
            off ^= (off >> 3) & 0x30;            // SW64
            *(uint4*)(smem + stg + off)         = rah[i];
            *(uint4*)(smem + stg + 8192 + off)  = ral[i];
            *(uint4*)(smem + stg + 16384 + off) = rbh[i];
            *(uint4*)(smem + stg + 24576 + off) = rbl[i];
        }
        fence_async_smem();
    };

    int ph[2] = {0, 0};
    ldg_tile(0);
    sts_tile(0);
    __syncthreads();

    const int NIT = K / 32;
    for (int it = 0; it < NIT; it++) {
        const int s = it & 1;
        if (it + 1 < NIT) ldg_tile(it + 1);
        if (wid == 0) {
            if (elect_one()) {
                const uint32_t stg = 1024u + (uint32_t)s * 32768u;
                uint64_t dAh = make_desc64(sb + stg);
                uint64_t dAl = make_desc64(sb + stg + 8192);
                uint64_t dBh = make_desc64(sb + stg + 16384);
                uint64_t dBl = make_desc64(sb + stg + 24576);
                #pragma unroll
                for (int ks = 0; ks < 2; ks++)
                    mma_bf16_ss(tmem, dAh + ks * 2, dBh + ks * 2, IDESC_BF_128x128, (it > 0) || (ks > 0));
                #pragma unroll
                for (int ks = 0; ks < 2; ks++)
                    mma_bf16_ss(tmem, dAl + ks * 2, dBh + ks * 2, IDESC_BF_128x128, true);
                #pragma unroll
                for (int ks = 0; ks < 2; ks++)
                    mma_bf16_ss(tmem, dAh + ks * 2, dBl + ks * 2, IDESC_BF_128x128, true);
                TCGEN05_COMMIT(sb + OFF_MB + s * 8);
            }
        }
        if (it + 1 < NIT) {
            const int so = s ^ 1;
            if (it >= 1) { mbar_wait(sb + OFF_MB + so * 8, ph[so]); ph[so] ^= 1; }
            sts_tile(so);
        }
        __syncthreads();
    }
    mbar_wait(sb + OFF_MB + ((NIT - 1) & 1) * 8, ph[(NIT - 1) & 1]);
    TCGEN05_FENCE_AFTER();

    if (tid < 128) {
        const int r = bm + tid;
        if (EPI == 0) {
            #pragma unroll
            for (int hb = 0; hb < 128; hb += 64) {
                uint32_t dr[64];
                TC_LD_X32(dr, tmem + hb);
                TC_LD_X32(dr + 32, tmem + hb + 32);
                TCGEN05_WAIT_LD();
                if (r < M) {
                    const int c0 = bn + hb;
                    const int which = c0 >> 10;
                    const int h = (c0 & 1023) >> 6;
                    float vbuf[64];
                    #pragma unroll
                    for (int j = 0; j < 64; j++)
                        vbuf[j] = __uint_as_float(dr[j]) + bias[c0 + j];
                    const int b = r / NTOK, n = r % NTOK;
                    if (which < 2 && n >= 1) {
                        const float* sr = &sinp[(size_t)(n - 1) * DHEAD];
                        const float* cr = &cosp[(size_t)(n - 1) * DHEAD];
                        #pragma unroll
                        for (int d = 0; d < 32; d++) {
                            float x1 = vbuf[d], x2 = vbuf[d + 32];
                            vbuf[d]      = x1 * cr[d]      - x2 * sr[d];
                            vbuf[d + 32] = x2 * cr[d + 32] + x1 * sr[d + 32];
                        }
                    }
                    float* dst = (which == 0) ? g_q : (which == 1) ? g_k : g_v;
                    size_t base = (((size_t)b * NHEAD + h) * NTOK + n) * DHEAD;
                    #pragma unroll
                    for (int d = 0; d < 64; d += 4)
                        *(float4*)&dst[base + d] = make_float4(vbuf[d], vbuf[d+1], vbuf[d+2], vbuf[d+3]);
                }
            }
        } else {
            #pragma unroll
            for (int cb = 0; cb < 128; cb += 32) {
                uint32_t dr[32];
                TC_LD_X32(dr, tmem + cb);
                TCGEN05_WAIT_LD();
                if (r < M) {
                    const int c0 = bn + cb;
                    #pragma unroll
                    for (int j = 0; j < 32; j += 4) {
                        float4 v = make_float4(__uint_as_float(dr[j])     + bias[c0 + j],
                                               __uint_as_float(dr[j + 1]) + bias[c0 + j + 1],
                                               __uint_as_float(dr[j + 2]) + bias[c0 + j + 2],
                                               __uint_as_float(dr[j + 3]) + bias[c0 + j + 3]);
                        *(float4*)&Out[(size_t)r * CDIM + c0 + j] = v;
                    }
                }
            }
        }
    }
    __syncthreads();
    if (wid == 0) TCGEN05_DEALLOC(tmem, 128);
#endif
}

// ---------------------------------------------------------------------------
// Tensor-core flash attention — R13-exact structure (best: 219us, 2 CTAs/SM),
// only the epilogue changed: writes bf16 hi/lo planes (g_aoh/g_aol) so the
// proj GEMM loader is copy-only.
// TMEM (256): O@0(64), S/Ph@64(32, shared), Pl@96(32), Qh@128(64), Ql@192(64)
// ---------------------------------------------------------------------------
#define ATT_SMEM 66560
#define NCHUNK 43

__global__ __launch_bounds__(256, 2) void attn_tc() {
#if TC_OK
    extern __shared__ char smem[];
    const uint32_t sb = smem_u32(smem);
    const int tid = threadIdx.x;
    const int wid = tid >> 5;
    const int bh = blockIdx.y;
    const int qt = blockIdx.x;
    const uint32_t MB_S = sb + 8, MB_O = sb + 16;

    if (wid == 0) { TCGEN05_ALLOC(sb, 256); TCGEN05_RELINQ(); }
    if (tid == 0) { mbar_init(MB_S, 1); mbar_init(MB_O, 1); }
    __syncthreads();
    uint32_t tmem;
    asm volatile("ld.shared.b32 %0, [%1];" : "=r"(tmem) : "r"(sb));

    // ---- Q hi/lo (tf32) -> TMEM (Qh@128, Ql@192) ----
    if (tid < 128) {
        int qrow = qt * 128 + tid; if (qrow > NTOK - 1) qrow = NTOK - 1;
        const float* Qp = g_q + ((size_t)bh * NTOK + qrow) * DHEAD;
        uint32_t qh0[32], qh1[32], ql0[32], ql1[32];
        #pragma unroll
        for (int i = 0; i < 32; i++) {
            float a = Qp[i], b = Qp[32 + i];
            float ah = tf32r(a), bhh = tf32r(b);
            qh0[i] = __float_as_uint(ah); ql0[i] = __float_as_uint(a - ah);
            qh1[i] = __float_as_uint(bhh); ql1[i] = __float_as_uint(b - bhh);
        }
        uint32_t woff = (uint32_t)(tid >> 5) << 21;
        TC_ST_X32(tmem + 128 + woff, qh0);
        TC_ST_X32(tmem + 160 + woff, qh1);
        TC_ST_X32(tmem + 192 + woff, ql0);
        TC_ST_X32(tmem + 224 + woff, ql1);
        TCGEN05_WAIT_ST();
        TCGEN05_FENCE_BEFORE();
    }

    auto load_chunk = [&](int c, int b) {
        const int k0 = c * 32;
        const uint32_t kb = 1024u  + (uint32_t)b * 16384u;
        const uint32_t vb = 33792u + (uint32_t)b * 16384u;
        #pragma unroll
        for (int i = 0; i < 2; i++) {           // K tile [32 rows][64 d], hi/lo split
            int idx = tid + i * 256;
            int row = idx >> 4, c4 = idx & 15;
            int gk = k0 + row; if (gk > NTOK - 1) gk = NTOK - 1;
            float4 v = *(const float4*)&g_k[((size_t)bh * NTOK + gk) * DHEAD + c4 * 4];
            float4 h = make_float4(tf32r(v.x), tf32r(v.y), tf32r(v.z), tf32r(v.w));
            float4 lo = make_float4(v.x - h.x, v.y - h.y, v.z - h.z, v.w - h.w);
            uint32_t off = (uint32_t)((c4 >> 3) * 4096 + row * 128) +
                           ((uint32_t)((c4 & 7) * 16) ^ (uint32_t)((row & 7) << 4));
            *(float4*)(smem + kb + off)        = h;
            *(float4*)(smem + kb + 8192 + off) = lo;
        }
        #pragma unroll
        for (int i = 0; i < 2; i++) {           // VT hi [64 rows(d)][32 k]
            int idx = tid + i * 256;
            int row = idx >> 3, c4 = idx & 7;
            float4 v = *(const float4*)&g_vth[((size_t)bh * DHEAD + row) * NPAD + k0 + c4 * 4];
            uint32_t off = (uint32_t)(row * 128) + ((uint32_t)(c4 * 16) ^ (uint32_t)((row & 7) << 4));
            *(float4*)(smem + vb + off) = v;
        }
        #pragma unroll
        for (int i = 0; i < 2; i++) {           // VT lo
            int idx = tid + i * 256;
            int row = idx >> 3, c4 = idx & 7;
            float4 v = *(const float4*)&g_vtl[((size_t)bh * DHEAD + row) * NPAD + k0 + c4 * 4];
            uint32_t off = (uint32_t)(row * 128) + ((uint32_t)(c4 * 16) ^ (uint32_t)((row & 7) << 4));
            *(float4*)(smem + vb + 8192 + off) = v;
        }
        fence_async_smem();
    };

    load_chunk(0, 0);
    __syncthreads();

    float l = 0.f;
    const float C1 = 0.18033688011112042f;     // 0.125 * log2(e)
    const uint32_t subp = (uint32_t)(wid & 3) << 21;
    const uint32_t colh = (uint32_t)(wid >> 2) << 4;   // 0 or 16
    const int jbase = (wid >> 2) * 16;

    for (int c = 0; c < NCHUNK; c++) {
        const int b = c & 1;
        // S-MMA(c): S[128,32] = 3xTF32( Q * K(b)^T )
        if (wid == 0) {
            TCGEN05_FENCE_AFTER();
            if (elect_one()) {
                uint64_t dKh = make_desc(sb + 1024u + (uint32_t)b * 16384u);
                uint64_t dKl = make_desc(sb + 1024u + (uint32_t)b * 16384u + 8192u);
                #pragma unroll
                for (int ks = 0; ks < 8; ks++)
                    mma_tf32_ts(tmem + 64, tmem + 128 + ks * 8,
                                dKh + (ks >> 2) * 256 + (ks & 3) * 2, IDESC_128x32, ks > 0);
                #pragma unroll
                for (int ks = 0; ks < 8; ks++)
                    mma_tf32_ts(tmem + 64, tmem + 192 + ks * 8,
                                dKh + (ks >> 2) * 256 + (ks & 3) * 2, IDESC_128x32, true);
                #pragma unroll
                for (int ks = 0; ks < 8; ks++)
                    mma_tf32_ts(tmem + 64, tmem + 128 + ks * 8,
                                dKl + (ks >> 2) * 256 + (ks & 3) * 2, IDESC_128x32, true);
                TCGEN05_COMMIT(MB_S);
            }
        }
        if (c >= 1) mbar_wait(MB_O, (c - 1) & 1);     // PV(c-1) done
        if (c + 1 < NCHUNK) load_chunk(c + 1, b ^ 1);

        // ---- softmax: all 8 warps, 16 cols each ----
        mbar_wait(MB_S, c & 1);
        TCGEN05_FENCE_AFTER();
        {
            uint32_t sr[16];
            TC_LD_X16(sr, tmem + 64 + colh + subp);
            TCGEN05_WAIT_LD();
            const int nk = NTOK - c * 32;
            uint32_t prh[16], prl[16];
            float lsum = 0.f;
            #pragma unroll
            for (int j = 0; j < 16; j++) {
                float s = __uint_as_float(sr[j]);
                float p = ex2f(fmaf(s, C1, -40.f));
                if (jbase + j >= nk) p = 0.f;
                lsum += p;
                float h = tf32r(p);
                prh[j] = __float_as_uint(h);
                prl[j] = __float_as_uint(p - h);
            }
            l += lsum;
            TC_ST_X16(tmem + 64 + colh + subp, prh);  // Ph overwrites consumed S
            TC_ST_X16(tmem + 96 + colh + subp, prl);
            TCGEN05_WAIT_ST();
            TCGEN05_FENCE_BEFORE();
        }
        __syncthreads();
        // PV(c): O += Ph*Vh + Pl*Vh + Ph*Vl
        if (wid == 0) {
            TCGEN05_FENCE_AFTER();
            if (elect_one()) {
                uint64_t dVh = make_desc(sb + 33792u + (uint32_t)b * 16384u);
                uint64_t dVl = make_desc(sb + 33792u + (uint32_t)b * 16384u + 8192u);
                #pragma unroll
                for (int ks = 0; ks < 4; ks++)
                    mma_tf32_ts(tmem + 0, tmem + 64 + ks * 8, dVh + ks * 2, IDESC_128x64, (c > 0) || (ks > 0));
                #pragma unroll
                for (int ks = 0; ks < 4; ks++)
                    mma_tf32_ts(tmem + 0, tmem + 96 + ks * 8, dVh + ks * 2, IDESC_128x64, true);
                #pragma unroll
                for (int ks = 0; ks < 4; ks++)
                    mma_tf32_ts(tmem + 0, tmem + 64 + ks * 8, dVl + ks * 2, IDESC_128x64, true);
                TCGEN05_COMMIT(MB_O);
            }
        }
    }

    mbar_wait(MB_O, (NCHUNK - 1) & 1);
    TCGEN05_FENCE_AFTER();
    // combine l partials: warps 4-7 publish, warps 0-3 add
    if (wid >= 4) ((float*)(smem + 512))[tid - 128] = l;
    __syncthreads();
    if (tid < 128) {
        float ltot = l + ((float*)(smem + 512))[tid];
        uint32_t o1[32], o2[32];
        TC_LD_X32(o1, tmem + 0);
        TC_LD_X32(o2, tmem + 32);
        TCGEN05_WAIT_LD();
        int qrow = qt * 128 + tid;
        if (qrow < NTOK) {
            float inv = 1.f / ltot;
            int bb = bh >> 4, h = bh & 15;
            size_t base = ((size_t)(bb * NTOK + qrow)) * CDIM + h * DHEAD;
            float o[64];
            #pragma unroll
            for (int d = 0; d < 32; d++) { o[d] = __uint_as_float(o1[d]) * inv; o[32 + d] = __uint_as_float(o2[d]) * inv; }
            // write bf16 hi/lo planes for the proj GEMM (copy-only loader)
            #pragma unroll
            for (int d = 0; d < 64; d += 4) {
                uint2 hi, lo;
                hi.x = bfpack(o[d], o[d+1]); hi.y = bfpack(o[d+2], o[d+3]);
                float r0 = o[d]   - __bfloat162float(__float2bfloat16(o[d]));
                float r1 = o[d+1] - __bfloat162float(__float2bfloat16(o[d+1]));
                float r2 = o[d+2] - __bfloat162float(__float2bfloat16(o[d+2]));
                float r3 = o[d+3] - __bfloat162float(__float2bfloat16(o[d+3]));
                lo.x = bfpack(r0, r1); lo.y = bfpack(r2, r3);
                *(uint2*)&g_aoh[base + d] = hi;
                *(uint2*)&g_aol[base + d] = lo;
            }
        }
    }
    __syncthreads();
    if (wid == 0) TCGEN05_DEALLOC(tmem, 256);
#endif
}

// ---------------------------------------------------------------------------
extern "C" void kernel_launch(void* const* d_in, const int* in_sizes, int n_in,
                              void* d_out, int out_size) {
    const float* x      = (const float*)d_in[0];
    const float* sinp   = (const float*)d_in[1];
    const float* cosp   = (const float*)d_in[2];
    const float* w_qkv  = (const float*)d_in[3];
    const float* b_qkv  = (const float*)d_in[4];
    const float* w_proj = (const float*)d_in[5];
    const float* b_proj = (const float*)d_in[6];
    float* out = (float*)d_out;

    cudaFuncSetAttribute(gemm_tc<0>, cudaFuncAttributeMaxDynamicSharedMemorySize, GSMEM_BYTES);
    cudaFuncSetAttribute(gemm_tc<1>, cudaFuncAttributeMaxDynamicSharedMemorySize, GSMEM_BYTES);
    cudaFuncSetAttribute(attn_tc,    cudaFuncAttributeMaxDynamicSharedMemorySize, ATT_SMEM);

    __nv_bfloat16 *xh, *xl, *wqh, *wql, *wph, *wpl, *aoh, *aol;
    cudaGetSymbolAddress((void**)&xh,  g_xh);
    cudaGetSymbolAddress((void**)&xl,  g_xl);
    cudaGetSymbolAddress((void**)&wqh, g_wqh);
    cudaGetSymbolAddress((void**)&wql, g_wql);
    cudaGetSymbolAddress((void**)&wph, g_wph);
    cudaGetSymbolAddress((void**)&wpl, g_wpl);
    cudaGetSymbolAddress((void**)&aoh, g_aoh);
    cudaGetSymbolAddress((void**)&aol, g_aol);

    {
        int total = MROWS * CDIM / 4;
        split_x<<<(total + 255) / 256, 256>>>(x);
    }
    transpose_w2<<<dim3(3 * CDIM / 32, CDIM / 32, 2), dim3(32, 8)>>>(w_qkv, w_proj);

    dim3 gq(3 * CDIM / 128, (MROWS + 127) / 128);   // 24 x 43
    gemm_tc<0><<<gq, 256, GSMEM_BYTES>>>(xh, xl, wqh, wql, b_qkv, sinp, cosp, nullptr, MROWS);

    transpose_v<<<dim3(2, NPAD / 32, BATCH * NHEAD), dim3(32, 8)>>>();

    dim3 ga((NTOK + 127) / 128, BATCH * NHEAD);     // 11 x 64
    attn_tc<<<ga, 256, ATT_SMEM>>>();

    dim3 gp(CDIM / 128, (MROWS + 127) / 128);       // 8 x 43
    gemm_tc<1><<<gp, 256, GSMEM_BYTES>>>(aoh, aol, wph, wpl, b_proj, nullptr, nullptr, out, MROWS);
}

// round 16
// speedup vs baseline: 1.1794x; 1.0265x over previous
#include <cuda_runtime.h>
#include <cuda_bf16.h>
#include <cstdint>

#if defined(__CUDA_ARCH_FEAT_SM103_ALL) || defined(__CUDA_ARCH_FEAT_SM100_ALL)
#define TC_OK 1
#else
#define TC_OK 0
#endif

#define BATCH 4
#define NTOK 1370
#define CDIM 1024
#define NHEAD 16
#define DHEAD 64
#define MROWS (BATCH*NTOK)   // 5480
#define NPAD 1408

// ---------------- scratch ----------------
__device__ float g_v [(size_t)BATCH*NHEAD*NTOK*DHEAD];
// pre-split bf16 planes
__device__ __nv_bfloat16 g_qhb[(size_t)BATCH*NHEAD*NTOK*DHEAD];
__device__ __nv_bfloat16 g_qlb[(size_t)BATCH*NHEAD*NTOK*DHEAD];
__device__ __nv_bfloat16 g_khb[(size_t)BATCH*NHEAD*NTOK*DHEAD];
__device__ __nv_bfloat16 g_klb[(size_t)BATCH*NHEAD*NTOK*DHEAD];
__device__ __nv_bfloat16 g_vthb[(size_t)BATCH*NHEAD*DHEAD*NPAD];
__device__ __nv_bfloat16 g_vtlb[(size_t)BATCH*NHEAD*DHEAD*NPAD];
__device__ __nv_bfloat16 g_xh[(size_t)MROWS*CDIM];
__device__ __nv_bfloat16 g_xl[(size_t)MROWS*CDIM];
__device__ __nv_bfloat16 g_wqh[(size_t)3*CDIM*CDIM];
__device__ __nv_bfloat16 g_wql[(size_t)3*CDIM*CDIM];
__device__ __nv_bfloat16 g_wph[(size_t)CDIM*CDIM];
__device__ __nv_bfloat16 g_wpl[(size_t)CDIM*CDIM];
__device__ __nv_bfloat16 g_aoh[(size_t)MROWS*CDIM];
__device__ __nv_bfloat16 g_aol[(size_t)MROWS*CDIM];

// ---------------- helpers ----------------
__device__ __forceinline__ uint32_t smem_u32(const void* p) {
    uint32_t a;
    asm("{ .reg .u64 t; cvta.to.shared.u64 t, %1; cvt.u32.u64 %0, t; }" : "=r"(a) : "l"(p));
    return a;
}
__device__ __forceinline__ uint32_t elect_one() {
    uint32_t pred;
    asm volatile("{\n\t.reg .pred p;\n\telect.sync _|p, 0xFFFFFFFF;\n\tselp.b32 %0, 1, 0, p;\n\t}" : "=r"(pred));
    return pred;
}
__device__ __forceinline__ float ex2f(float x) {
    float y; asm("ex2.approx.ftz.f32 %0, %1;" : "=f"(y) : "f"(x)); return y;
}
__device__ __forceinline__ uint32_t bfpack(float a, float b) {
    __nv_bfloat16 ha = __float2bfloat16(a), hb = __float2bfloat16(b);
    return (uint32_t)*(uint16_t*)&ha | ((uint32_t)*(uint16_t*)&hb << 16);
}
__device__ __forceinline__ void mbar_init(uint32_t mbar, uint32_t cnt) {
    asm volatile("mbarrier.init.shared.b64 [%0], %1;" :: "r"(mbar), "r"(cnt) : "memory");
}
__device__ __forceinline__ void mbar_wait(uint32_t mbar, uint32_t parity) {
    asm volatile(
        "{\n\t.reg .pred P;\n\t"
        "WL_%=:\n\t"
        "mbarrier.try_wait.parity.acquire.cta.shared::cta.b64 P, [%0], %1, 0x989680;\n\t"
        "@P bra.uni WD_%=;\n\t"
        "bra.uni WL_%=;\n\t"
        "WD_%=:\n\t}"
        :: "r"(mbar), "r"(parity) : "memory");
}
__device__ __forceinline__ void fence_async_smem() {
    asm volatile("fence.proxy.async.shared::cta;" ::: "memory");
}

#if TC_OK
#define TCGEN05_ALLOC(sm, n)  asm volatile("tcgen05.alloc.cta_group::1.sync.aligned.shared::cta.b32 [%0], %1;" :: "r"(sm), "r"(n) : "memory")
#define TCGEN05_DEALLOC(t, n) asm volatile("tcgen05.dealloc.cta_group::1.sync.aligned.b32 %0, %1;" :: "r"(t), "r"(n))
#define TCGEN05_RELINQ()      asm volatile("tcgen05.relinquish_alloc_permit.cta_group::1.sync.aligned;")
#define TCGEN05_COMMIT(mb)    asm volatile("tcgen05.commit.cta_group::1.mbarrier::arrive::one.shared::cluster.b64 [%0];" :: "r"(mb) : "memory")
#define TCGEN05_WAIT_LD()     asm volatile("tcgen05.wait::ld.sync.aligned;" ::: "memory")
#define TCGEN05_WAIT_ST()     asm volatile("tcgen05.wait::st.sync.aligned;" ::: "memory")
#define TCGEN05_FENCE_BEFORE() asm volatile("tcgen05.fence::before_thread_sync;" ::: "memory")
#define TCGEN05_FENCE_AFTER()  asm volatile("tcgen05.fence::after_thread_sync;" ::: "memory")

#define TC_LD_X32(r, addr) \
    asm volatile( \
        "tcgen05.ld.sync.aligned.32x32b.x32.b32 " \
        "{%0, %1, %2, %3, %4, %5, %6, %7, " \
        " %8, %9, %10, %11, %12, %13, %14, %15, " \
        " %16, %17, %18, %19, %20, %21, %22, %23, " \
        " %24, %25, %26, %27, %28, %29, %30, %31}, [%32];" \
        : "=r"((r)[0]),  "=r"((r)[1]),  "=r"((r)[2]),  "=r"((r)[3]), \
          "=r"((r)[4]),  "=r"((r)[5]),  "=r"((r)[6]),  "=r"((r)[7]), \
          "=r"((r)[8]),  "=r"((r)[9]),  "=r"((r)[10]), "=r"((r)[11]), \
          "=r"((r)[12]), "=r"((r)[13]), "=r"((r)[14]), "=r"((r)[15]), \
          "=r"((r)[16]), "=r"((r)[17]), "=r"((r)[18]), "=r"((r)[19]), \
          "=r"((r)[20]), "=r"((r)[21]), "=r"((r)[22]), "=r"((r)[23]), \
          "=r"((r)[24]), "=r"((r)[25]), "=r"((r)[26]), "=r"((r)[27]), \
          "=r"((r)[28]), "=r"((r)[29]), "=r"((r)[30]), "=r"((r)[31]) \
        : "r"(addr))

#define TC_ST_X32(addr, r) \
    asm volatile( \
        "tcgen05.st.sync.aligned.32x32b.x32.b32 [%0], " \
        "{%1, %2, %3, %4, %5, %6, %7, %8, " \
        " %9, %10, %11, %12, %13, %14, %15, %16, " \
        " %17, %18, %19, %20, %21, %22, %23, %24, " \
        " %25, %26, %27, %28, %29, %30, %31, %32};" \
        :: "r"(addr), \
           "r"((r)[0]),  "r"((r)[1]),  "r"((r)[2]),  "r"((r)[3]), \
           "r"((r)[4]),  "r"((r)[5]),  "r"((r)[6]),  "r"((r)[7]), \
           "r"((r)[8]),  "r"((r)[9]),  "r"((r)[10]), "r"((r)[11]), \
           "r"((r)[12]), "r"((r)[13]), "r"((r)[14]), "r"((r)[15]), \
           "r"((r)[16]), "r"((r)[17]), "r"((r)[18]), "r"((r)[19]), \
           "r"((r)[20]), "r"((r)[21]), "r"((r)[22]), "r"((r)[23]), \
           "r"((r)[24]), "r"((r)[25]), "r"((r)[26]), "r"((r)[27]), \
           "r"((r)[28]), "r"((r)[29]), "r"((r)[30]), "r"((r)[31]) \
        : "memory")

#define TC_LD_X16(r, addr) \
    asm volatile( \
        "tcgen05.ld.sync.aligned.32x32b.x16.b32 " \
        "{%0, %1, %2, %3, %4, %5, %6, %7, " \
        " %8, %9, %10, %11, %12, %13, %14, %15}, [%16];" \
        : "=r"((r)[0]),  "=r"((r)[1]),  "=r"((r)[2]),  "=r"((r)[3]), \
          "=r"((r)[4]),  "=r"((r)[5]),  "=r"((r)[6]),  "=r"((r)[7]), \
          "=r"((r)[8]),  "=r"((r)[9]),  "=r"((r)[10]), "=r"((r)[11]), \
          "=r"((r)[12]), "=r"((r)[13]), "=r"((r)[14]), "=r"((r)[15]) \
        : "r"(addr))

#define TC_ST_X8(addr, r) \
    asm volatile( \
        "tcgen05.st.sync.aligned.32x32b.x8.b32 [%0], " \
        "{%1, %2, %3, %4, %5, %6, %7, %8};" \
        :: "r"(addr), \
           "r"((r)[0]),  "r"((r)[1]),  "r"((r)[2]),  "r"((r)[3]), \
           "r"((r)[4]),  "r"((r)[5]),  "r"((r)[6]),  "r"((r)[7]) \
        : "memory")

// K-major SW128 descriptor (128B rows)
static __device__ __forceinline__ uint64_t make_desc(uint32_t addr) {
    const uint64_t BASE = (2ull << 61) | (1ull << 46) | (64ull << 32) | (1ull << 16);
    return BASE | ((uint64_t)(addr >> 4) & 0x3FFF);
}
// K-major SW64 descriptor (64B rows)
static __device__ __forceinline__ uint64_t make_desc64(uint32_t addr) {
    const uint64_t BASE = (4ull << 61) | (1ull << 46) | (32ull << 32) | (1ull << 16);
    return BASE | ((uint64_t)(addr >> 4) & 0x3FFF);
}
__device__ __forceinline__ void mma_bf16_ss(uint32_t d, uint64_t ad, uint64_t bd,
                                            uint32_t idesc, bool en) {
    uint32_t e = en ? 1u : 0u;
    asm volatile(
        "{\n\t.reg .pred p;\n\tsetp.ne.u32 p, %4, 0;\n\t"
        "tcgen05.mma.cta_group::1.kind::f16 [%0], %1, %2, %3, {%5, %5, %5, %5}, p;\n\t}"
        :: "r"(d), "l"(ad), "l"(bd), "r"(idesc), "r"(e), "r"(0u) : "memory");
}
__device__ __forceinline__ void mma_bf16_ts(uint32_t d, uint32_t a, uint64_t bd,
                                            uint32_t idesc, bool en) {
    uint32_t e = en ? 1u : 0u;
    asm volatile(
        "{\n\t.reg .pred p;\n\tsetp.ne.u32 p, %4, 0;\n\t"
        "tcgen05.mma.cta_group::1.kind::f16 [%0], [%1], %2, %3, {%5, %5, %5, %5}, p;\n\t}"
        :: "r"(d), "r"(a), "l"(bd), "r"(idesc), "r"(e), "r"(0u) : "memory");
}
#endif // TC_OK

static constexpr uint32_t IDESC_BF_128x128 =
    (1u << 4) | (1u << 7) | (1u << 10) | (16u << 17) | (8u << 24);
static constexpr uint32_t IDESC_BF_128x32 =
    (1u << 4) | (1u << 7) | (1u << 10) | (4u << 17) | (8u << 24);
static constexpr uint32_t IDESC_BF_128x64 =
    (1u << 4) | (1u << 7) | (1u << 10) | (8u << 17) | (8u << 24);

// ---------------------------------------------------------------------------
// prep: elementwise bf16 hi/lo split of x
// ---------------------------------------------------------------------------
__global__ void split_x(const float* __restrict__ x) {
    int i = blockIdx.x * blockDim.x + threadIdx.x;
    const int total = MROWS * CDIM / 4;
    if (i >= total) return;
    float4 v = ((const float4*)x)[i];
    uint2 hi, lo;
    hi.x = bfpack(v.x, v.y); hi.y = bfpack(v.z, v.w);
    float rx = v.x - __bfloat162float(__float2bfloat16(v.x));
    float ry = v.y - __bfloat162float(__float2bfloat16(v.y));
    float rz = v.z - __bfloat162float(__float2bfloat16(v.z));
    float rw = v.w - __bfloat162float(__float2bfloat16(v.w));
    lo.x = bfpack(rx, ry); lo.y = bfpack(rz, rw);
    ((uint2*)g_xh)[i] = hi;
    ((uint2*)g_xl)[i] = lo;
}

// ---------------------------------------------------------------------------
// prep: transpose both weight matrices + bf16 hi/lo split
// ---------------------------------------------------------------------------
__global__ void transpose_w2(const float* __restrict__ wqkv, const float* __restrict__ wproj) {
    const int z = blockIdx.z;
    const int C = z ? CDIM : 3 * CDIM;
    if (blockIdx.x * 32 >= (unsigned)C) return;
    const float* src = z ? wproj : wqkv;
    __nv_bfloat16* dh = z ? g_wph : g_wqh;
    __nv_bfloat16* dl = z ? g_wpl : g_wql;
    __shared__ float t[32][33];
    int bx = blockIdx.x * 32, by = blockIdx.y * 32;
    int txx = threadIdx.x, tyy = threadIdx.y;
    #pragma unroll
    for (int i = 0; i < 4; i++)
        t[tyy + i * 8][txx] = src[(size_t)(by + tyy + i * 8) * C + bx + txx];
    __syncthreads();
    #pragma unroll
    for (int i = 0; i < 4; i++) {
        float v = t[txx][tyy + i * 8];
        __nv_bfloat16 h = __float2bfloat16(v);
        float r = v - __bfloat162float(h);
        size_t o = (size_t)(bx + tyy + i * 8) * CDIM + by + txx;
        dh[o] = h;
        dl[o] = __float2bfloat16(r);
    }
}

// ---------------------------------------------------------------------------
// prep: per-head V transpose + bf16 hi/lo split
// ---------------------------------------------------------------------------
__global__ void transpose_v() {
    __shared__ float t[32][33];
    int bh = blockIdx.z;
    int dt = blockIdx.x * 32, nt = blockIdx.y * 32;
    int txx = threadIdx.x, tyy = threadIdx.y;
    #pragma unroll
    for (int i = 0; i < 4; i++) {
        int n = nt + tyy + i * 8; if (n > NTOK - 1) n = NTOK - 1;
        t[tyy + i * 8][txx] = g_v[((size_t)bh * NTOK + n) * DHEAD + dt + txx];
    }
    __syncthreads();
    #pragma unroll
    for (int i = 0; i < 4; i++) {
        int d = dt + tyy + i * 8;
        float v = t[txx][tyy + i * 8];
        __nv_bfloat16 h = __float2bfloat16(v);
        float r = v - __bfloat162float(h);
        size_t o = ((size_t)bh * DHEAD + d) * NPAD + nt + txx;
        g_vthb[o] = h;
        g_vtlb[o] = __float2bfloat16(r);
    }
}

// ---------------------------------------------------------------------------
// bf16x3 GEMM (R15 exact) — EPI==0 epilogue now writes Q/K pre-split bf16.
// ---------------------------------------------------------------------------
#define GSMEM_BYTES (1024 + 2 * 32768)

template<int EPI>
__global__ __launch_bounds__(256, 2) void gemm_tc(const __nv_bfloat16* __restrict__ Ah,
                                                  const __nv_bfloat16* __restrict__ Al,
                                                  const __nv_bfloat16* __restrict__ Bh,
                                                  const __nv_bfloat16* __restrict__ Bl,
                                                  const float* __restrict__ bias,
                                                  const float* __restrict__ sinp,
                                                  const float* __restrict__ cosp,
                                                  float* __restrict__ Out, int M) {
#if TC_OK
    extern __shared__ char smem[];
    const uint32_t sb = smem_u32(smem);
    const int K = 1024;
    const int tid = threadIdx.x;
    const int wid = tid >> 5;

    const uint32_t OFF_TM = 0;
    const uint32_t OFF_MB = 16;
    if (wid == 0) { TCGEN05_ALLOC(sb + OFF_TM, 128); TCGEN05_RELINQ(); }
    if (tid == 0) { mbar_init(sb + OFF_MB, 1); mbar_init(sb + OFF_MB + 8, 1); }
    __syncthreads();
    uint32_t tmem;
    asm volatile("ld.shared.b32 %0, [%1];" : "=r"(tmem) : "r"(sb + OFF_TM));

    const int bm = blockIdx.y * 128;
    const int bn = blockIdx.x * 128;

    uint4 rah[2], ral[2], rbh[2], rbl[2];

    auto ldg_tile = [&](int it) {
        const int k0 = it * 32;
        #pragma unroll
        for (int i = 0; i < 2; i++) {
            int idx = tid + i * 256;
            int row = idx >> 2, seg = idx & 3;
            int gr = bm + row;
            int grc = (gr < M) ? gr : (M - 1);
            size_t ao = (size_t)grc * K + k0 + seg * 8;
            rah[i] = *(const uint4*)&Ah[ao];
            ral[i] = *(const uint4*)&Al[ao];
            if (gr >= M) { rah[i] = make_uint4(0,0,0,0); ral[i] = make_uint4(0,0,0,0); }
            size_t bo = (size_t)(bn + row) * K + k0 + seg * 8;
            rbh[i] = *(const uint4*)&Bh[bo];
            rbl[i] = *(const uint4*)&Bl[bo];
        }
    };
    auto sts_tile = [&](int s) {
        const uint32_t stg = 1024u + (uint32_t)s * 32768u;
        #pragma unroll
        for (int i = 0; i < 2; i++) {
            int idx = tid + i * 256;
            int row = idx >> 2, seg = idx & 3;
            uint32_t off = (uint32_t)(row * 64 + seg * 16);
            off ^= (off >> 3) & 0x30;            // SW64
            *(uint4*)(smem + stg + off)         = rah[i];
            *(uint4*)(smem + stg + 8192 + off)  = ral[i];
            *(uint4*)(smem + stg + 16384 + off) = rbh[i];
            *(uint4*)(smem + stg + 24576 + off) = rbl[i];
        }
        fence_async_smem();
    };

    int ph[2] = {0, 0};
    ldg_tile(0);
    sts_tile(0);
    __syncthreads();

    const int NIT = K / 32;
    for (int it = 0; it < NIT; it++) {
        const int s = it & 1;
        if (it + 1 < NIT) ldg_tile(it + 1);
        if (wid == 0) {
            if (elect_one()) {
                const uint32_t stg = 1024u + (uint32_t)s * 32768u;
                uint64_t dAh = make_desc64(sb + stg);
                uint64_t dAl = make_desc64(sb + stg + 8192);
                uint64_t dBh = make_desc64(sb + stg + 16384);
                uint64_t dBl = make_desc64(sb + stg + 24576);
                #pragma unroll
                for (int ks = 0; ks < 2; ks++)
                    mma_bf16_ss(tmem, dAh + ks * 2, dBh + ks * 2, IDESC_BF_128x128, (it > 0) || (ks > 0));
                #pragma unroll
                for (int ks = 0; ks < 2; ks++)
                    mma_bf16_ss(tmem, dAl + ks * 2, dBh + ks * 2, IDESC_BF_128x128, true);
                #pragma unroll
                for (int ks = 0; ks < 2; ks++)
                    mma_bf16_ss(tmem, dAh + ks * 2, dBl + ks * 2, IDESC_BF_128x128, true);
                TCGEN05_COMMIT(sb + OFF_MB + s * 8);
            }
        }
        if (it + 1 < NIT) {
            const int so = s ^ 1;
            if (it >= 1) { mbar_wait(sb + OFF_MB + so * 8, ph[so]); ph[so] ^= 1; }
            sts_tile(so);
        }
        __syncthreads();
    }
    mbar_wait(sb + OFF_MB + ((NIT - 1) & 1) * 8, ph[(NIT - 1) & 1]);
    TCGEN05_FENCE_AFTER();

    if (tid < 128) {
        const int r = bm + tid;
        if (EPI == 0) {
            #pragma unroll
            for (int hb = 0; hb < 128; hb += 64) {
                uint32_t dr[64];
                TC_LD_X32(dr, tmem + hb);
                TC_LD_X32(dr + 32, tmem + hb + 32);
                TCGEN05_WAIT_LD();
                if (r < M) {
                    const int c0 = bn + hb;
                    const int which = c0 >> 10;
                    const int h = (c0 & 1023) >> 6;
                    float vbuf[64];
                    #pragma unroll
                    for (int j = 0; j < 64; j++)
                        vbuf[j] = __uint_as_float(dr[j]) + bias[c0 + j];
                    const int b = r / NTOK, n = r % NTOK;
                    if (which < 2 && n >= 1) {
                        const float* sr = &sinp[(size_t)(n - 1) * DHEAD];
                        const float* cr = &cosp[(size_t)(n - 1) * DHEAD];
                        #pragma unroll
                        for (int d = 0; d < 32; d++) {
                            float x1 = vbuf[d], x2 = vbuf[d + 32];
                            vbuf[d]      = x1 * cr[d]      - x2 * sr[d];
                            vbuf[d + 32] = x2 * cr[d + 32] + x1 * sr[d + 32];
                        }
                    }
                    size_t base = (((size_t)(b * NHEAD + h)) * NTOK + n) * DHEAD;
                    if (which == 2) {
                        #pragma unroll
                        for (int d = 0; d < 64; d += 4)
                            *(float4*)&g_v[base + d] = make_float4(vbuf[d], vbuf[d+1], vbuf[d+2], vbuf[d+3]);
                    } else {
                        __nv_bfloat16* dsth = which ? g_khb : g_qhb;
                        __nv_bfloat16* dstl = which ? g_klb : g_qlb;
                        #pragma unroll
                        for (int d = 0; d < 64; d += 4) {
                            uint2 hi, lo;
                            hi.x = bfpack(vbuf[d], vbuf[d+1]); hi.y = bfpack(vbuf[d+2], vbuf[d+3]);
                            float r0 = vbuf[d]   - __bfloat162float(__float2bfloat16(vbuf[d]));
                            float r1 = vbuf[d+1] - __bfloat162float(__float2bfloat16(vbuf[d+1]));
                            float r2 = vbuf[d+2] - __bfloat162float(__float2bfloat16(vbuf[d+2]));
                            float r3 = vbuf[d+3] - __bfloat162float(__float2bfloat16(vbuf[d+3]));
                            lo.x = bfpack(r0, r1); lo.y = bfpack(r2, r3);
                            *(uint2*)&dsth[base + d] = hi;
                            *(uint2*)&dstl[base + d] = lo;
                        }
                    }
                }
            }
        } else {
            #pragma unroll
            for (int cb = 0; cb < 128; cb += 32) {
                uint32_t dr[32];
                TC_LD_X32(dr, tmem + cb);
                TCGEN05_WAIT_LD();
                if (r < M) {
                    const int c0 = bn + cb;
                    #pragma unroll
                    for (int j = 0; j < 32; j += 4) {
                        float4 v = make_float4(__uint_as_float(dr[j])     + bias[c0 + j],
                                               __uint_as_float(dr[j + 1]) + bias[c0 + j + 1],
                                               __uint_as_float(dr[j + 2]) + bias[c0 + j + 2],
                                               __uint_as_float(dr[j + 3]) + bias[c0 + j + 3]);
                        *(float4*)&Out[(size_t)r * CDIM + c0 + j] = v;
                    }
                }
            }
        }
    }
    __syncthreads();
    if (wid == 0) TCGEN05_DEALLOC(tmem, 128);
#endif
}

// ---------------------------------------------------------------------------
// Tensor-core flash attention — R13 skeleton, bf16x3 arithmetic, copy-only
// loads (all operands pre-split in gmem).
// TMEM (256): O@0(64 fp32), S@64(32 fp32), Ph@96(16), Pl@112(16),
//             Qh@128(32), Ql@160(32)
// SMEM stage b @1024+b*16384: Kh@0(4KB,SW128), Kl@4096, Vh@8192(4KB,SW64), Vl@12288
// ---------------------------------------------------------------------------
#define ATT_SMEM 33792
#define NCHUNK 43

__global__ __launch_bounds__(256, 2) void attn_tc() {
#if TC_OK
    extern __shared__ char smem[];
    const uint32_t sb = smem_u32(smem);
    const int tid = threadIdx.x;
    const int wid = tid >> 5;
    const int bh = blockIdx.y;
    const int qt = blockIdx.x;
    const uint32_t MB_S = sb + 8, MB_O = sb + 16;

    if (wid == 0) { TCGEN05_ALLOC(sb, 256); TCGEN05_RELINQ(); }
    if (tid == 0) { mbar_init(MB_S, 1); mbar_init(MB_O, 1); }
    __syncthreads();
    uint32_t tmem;
    asm volatile("ld.shared.b32 %0, [%1];" : "=r"(tmem) : "r"(sb));

    // ---- Q bf16 hi/lo -> TMEM (Qh@128, Ql@160), copy-only ----
    if (tid < 128) {
        int qrow = qt * 128 + tid; if (qrow > NTOK - 1) qrow = NTOK - 1;
        size_t qb = ((size_t)bh * NTOK + qrow) * DHEAD;
        uint32_t qh[32], ql[32];
        #pragma unroll
        for (int i = 0; i < 8; i++) {
            uint4 h = ((const uint4*)&g_qhb[qb])[i];
            uint4 l = ((const uint4*)&g_qlb[qb])[i];
            qh[i*4+0] = h.x; qh[i*4+1] = h.y; qh[i*4+2] = h.z; qh[i*4+3] = h.w;
            ql[i*4+0] = l.x; ql[i*4+1] = l.y; ql[i*4+2] = l.z; ql[i*4+3] = l.w;
        }
        uint32_t woff = (uint32_t)(tid >> 5) << 21;
        TC_ST_X32(tmem + 128 + woff, qh);
        TC_ST_X32(tmem + 160 + woff, ql);
        TCGEN05_WAIT_ST();
        TCGEN05_FENCE_BEFORE();
    }

    auto load_chunk = [&](int c, int b) {
        const int k0 = c * 32;
        const uint32_t kb = 1024u + (uint32_t)b * 16384u;
        const uint32_t vb = kb + 8192u;
        {   // K tile [32 rows][64 bf16 = 128B], SW128, copy-only
            int row = tid >> 3, c4 = tid & 7;
            int gk = k0 + row; if (gk > NTOK - 1) gk = NTOK - 1;
            size_t src = ((size_t)bh * NTOK + gk) * DHEAD;
            uint4 h = ((const uint4*)&g_khb[src])[c4];
            uint4 l = ((const uint4*)&g_klb[src])[c4];
            uint32_t off = (uint32_t)(row * 128) + (((uint32_t)(c4 * 16)) ^ (uint32_t)((row & 7) << 4));
            *(uint4*)(smem + kb + off)        = h;
            *(uint4*)(smem + kb + 4096 + off) = l;
        }
        {   // V^T tile [64 d rows][32 keys bf16 = 64B], SW64, copy-only
            int row = tid >> 2, seg = tid & 3;
            size_t src = ((size_t)bh * DHEAD + row) * NPAD + k0;
            uint4 h = ((const uint4*)&g_vthb[src])[seg];
            uint4 l = ((const uint4*)&g_vtlb[src])[seg];
            uint32_t off = (uint32_t)(row * 64 + seg * 16);
            off ^= (off >> 3) & 0x30;
            *(uint4*)(smem + vb + off)        = h;
            *(uint4*)(smem + vb + 4096 + off) = l;
        }
        fence_async_smem();
    };

    load_chunk(0, 0);
    __syncthreads();

    float l = 0.f;
    const float C1 = 0.18033688011112042f;     // 0.125 * log2(e)
    const uint32_t subp = (uint32_t)(wid & 3) << 21;
    const uint32_t colh = (uint32_t)(wid >> 2) << 4;   // 0 or 16
    const int jbase = (wid >> 2) * 16;

    for (int c = 0; c < NCHUNK; c++) {
        const int b = c & 1;
        // S-MMA(c): S[128,32] = bf16x3( Q * K(b)^T ), 4 K-steps per term
        if (wid == 0) {
            TCGEN05_FENCE_AFTER();
            if (elect_one()) {
                uint64_t dKh = make_desc(sb + 1024u + (uint32_t)b * 16384u);
                uint64_t dKl = make_desc(sb + 1024u + (uint32_t)b * 16384u + 4096u);
                #pragma unroll
                for (int ks = 0; ks < 4; ks++)
                    mma_bf16_ts(tmem + 64, tmem + 128 + ks * 8, dKh + ks * 2, IDESC_BF_128x32, ks > 0);
                #pragma unroll
                for (int ks = 0; ks < 4; ks++)
                    mma_bf16_ts(tmem + 64, tmem + 160 + ks * 8, dKh + ks * 2, IDESC_BF_128x32, true);
                #pragma unroll
                for (int ks = 0; ks < 4; ks++)
                    mma_bf16_ts(tmem + 64, tmem + 128 + ks * 8, dKl + ks * 2, IDESC_BF_128x32, true);
                TCGEN05_COMMIT(MB_S);
            }
        }
        if (c >= 1) mbar_wait(MB_O, (c - 1) & 1);     // PV(c-1) done
        if (c + 1 < NCHUNK) load_chunk(c + 1, b ^ 1);

        // ---- softmax: all 8 warps, 16 S cols each ----
        mbar_wait(MB_S, c & 1);
        TCGEN05_FENCE_AFTER();
        {
            uint32_t sr[16];
            TC_LD_X16(sr, tmem + 64 + colh + subp);
            TCGEN05_WAIT_LD();
            const int nk = NTOK - c * 32;
            float p[16];
            float lsum = 0.f;
            #pragma unroll
            for (int j = 0; j < 16; j++) {
                float s = __uint_as_float(sr[j]);
                float pp = ex2f(fmaf(s, C1, -40.f));
                if (jbase + j >= nk) pp = 0.f;
                lsum += pp;
                p[j] = pp;
            }
            l += lsum;
            uint32_t phw[8], plw[8];
            #pragma unroll
            for (int j = 0; j < 8; j++) {
                float a = p[2 * j], b2 = p[2 * j + 1];
                phw[j] = bfpack(a, b2);
                float ra = a - __bfloat162float(__float2bfloat16(a));
                float rb = b2 - __bfloat162float(__float2bfloat16(b2));
                plw[j] = bfpack(ra, rb);
            }
            const uint32_t pco = (uint32_t)(wid >> 2) * 8 + subp;
            TC_ST_X8(tmem + 96 + pco, phw);
            TC_ST_X8(tmem + 112 + pco, plw);
            TCGEN05_WAIT_ST();
            TCGEN05_FENCE_BEFORE();
        }
        __syncthreads();
        // PV(c): O[128,64] += Ph*Vh + Pl*Vh + Ph*Vl, 2 K-steps per term
        if (wid == 0) {
            TCGEN05_FENCE_AFTER();
            if (elect_one()) {
                uint64_t dVh = make_desc64(sb + 1024u + (uint32_t)b * 16384u + 8192u);
                uint64_t dVl = make_desc64(sb + 1024u + (uint32_t)b * 16384u + 12288u);
                #pragma unroll
                for (int ks = 0; ks < 2; ks++)
                    mma_bf16_ts(tmem + 0, tmem + 96 + ks * 8, dVh + ks * 2, IDESC_BF_128x64, (c > 0) || (ks > 0));
                #pragma unroll
                for (int ks = 0; ks < 2; ks++)
                    mma_bf16_ts(tmem + 0, tmem + 112 + ks * 8, dVh + ks * 2, IDESC_BF_128x64, true);
                #pragma unroll
                for (int ks = 0; ks < 2; ks++)
                    mma_bf16_ts(tmem + 0, tmem + 96 + ks * 8, dVl + ks * 2, IDESC_BF_128x64, true);
                TCGEN05_COMMIT(MB_O);
            }
        }
    }

    mbar_wait(MB_O, (NCHUNK - 1) & 1);
    TCGEN05_FENCE_AFTER();
    if (wid >= 4) ((float*)(smem + 512))[tid - 128] = l;
    __syncthreads();
    if (tid < 128) {
        float ltot = l + ((float*)(smem + 512))[tid];
        uint32_t o1[32], o2[32];
        TC_LD_X32(o1, tmem + 0);
        TC_LD_X32(o2, tmem + 32);
        TCGEN05_WAIT_LD();
        int qrow = qt * 128 + tid;
        if (qrow < NTOK) {
            float inv = 1.f / ltot;
            int bb = bh >> 4, h = bh & 15;
            size_t base = ((size_t)(bb * NTOK + qrow)) * CDIM + h * DHEAD;
            float o[64];
            #pragma unroll
            for (int d = 0; d < 32; d++) { o[d] = __uint_as_float(o1[d]) * inv; o[32 + d] = __uint_as_float(o2[d]) * inv; }
            #pragma unroll
            for (int d = 0; d < 64; d += 4) {
                uint2 hi, lo;
                hi.x = bfpack(o[d], o[d+1]); hi.y = bfpack(o[d+2], o[d+3]);
                float r0 = o[d]   - __bfloat162float(__float2bfloat16(o[d]));
                float r1 = o[d+1] - __bfloat162float(__float2bfloat16(o[d+1]));
                float r2 = o[d+2] - __bfloat162float(__float2bfloat16(o[d+2]));
                float r3 = o[d+3] - __bfloat162float(__float2bfloat16(o[d+3]));
                lo.x = bfpack(r0, r1); lo.y = bfpack(r2, r3);
                *(uint2*)&g_aoh[base + d] = hi;
                *(uint2*)&g_aol[base + d] = lo;
            }
        }
    }
    __syncthreads();
    if (wid == 0) TCGEN05_DEALLOC(tmem, 256);
#endif
}

// ---------------------------------------------------------------------------
extern "C" void kernel_launch(void* const* d_in, const int* in_sizes, int n_in,
                              void* d_out, int out_size) {
    const float* x      = (const float*)d_in[0];
    const float* sinp   = (const float*)d_in[1];
    const float* cosp   = (const float*)d_in[2];
    const float* w_qkv  = (const float*)d_in[3];
    const float* b_qkv  = (const float*)d_in[4];
    const float* w_proj = (const float*)d_in[5];
    const float* b_proj = (const float*)d_in[6];
    float* out = (float*)d_out;

    cudaFuncSetAttribute(gemm_tc<0>, cudaFuncAttributeMaxDynamicSharedMemorySize, GSMEM_BYTES);
    cudaFuncSetAttribute(gemm_tc<1>, cudaFuncAttributeMaxDynamicSharedMemorySize, GSMEM_BYTES);
    cudaFuncSetAttribute(attn_tc,    cudaFuncAttributeMaxDynamicSharedMemorySize, ATT_SMEM);

    __nv_bfloat16 *xh, *xl, *wqh, *wql, *wph, *wpl, *aoh, *aol;
    cudaGetSymbolAddress((void**)&xh,  g_xh);
    cudaGetSymbolAddress((void**)&xl,  g_xl);
    cudaGetSymbolAddress((void**)&wqh, g_wqh);
    cudaGetSymbolAddress((void**)&wql, g_wql);
    cudaGetSymbolAddress((void**)&wph, g_wph);
    cudaGetSymbolAddress((void**)&wpl, g_wpl);
    cudaGetSymbolAddress((void**)&aoh, g_aoh);
    cudaGetSymbolAddress((void**)&aol, g_aol);

    {
        int total = MROWS * CDIM / 4;
        split_x<<<(total + 255) / 256, 256>>>(x);
    }
    transpose_w2<<<dim3(3 * CDIM / 32, CDIM / 32, 2), dim3(32, 8)>>>(w_qkv, w_proj);

    dim3 gq(3 * CDIM / 128, (MROWS + 127) / 128);   // 24 x 43
    gemm_tc<0><<<gq, 256, GSMEM_BYTES>>>(xh, xl, wqh, wql, b_qkv, sinp, cosp, nullptr, MROWS);

    transpose_v<<<dim3(2, NPAD / 32, BATCH * NHEAD), dim3(32, 8)>>>();

    dim3 ga((NTOK + 127) / 128, BATCH * NHEAD);     // 11 x 64
    attn_tc<<<ga, 256, ATT_SMEM>>>();

    dim3 gp(CDIM / 128, (MROWS + 127) / 128);       // 8 x 43
    gemm_tc<1><<<gp, 256, GSMEM_BYTES>>>(aoh, aol, wph, wpl, b_proj, nullptr, nullptr, out, MROWS);
}